// round 8
// baseline (speedup 1.0000x reference)
#include <cuda_runtime.h>
#include <cstdint>
#include <math.h>

// Problem dims (fixed by the reference)
#define BB 32
#define SS 512
#define DD 1024
#define HH 16
#define DK 64
#define FF 4096
#define MM (BB*SS)   // 16384 rows

// ---------------------------------------------------------------------------
// Scratch (static device arrays; no allocation APIs anywhere)
// ---------------------------------------------------------------------------
__device__ float g_q  [BB*HH*SS*DK];   // [B,H,S,dk], pre-scaled by 1/sqrt(dk), tf32-grid
__device__ float g_k  [BB*HH*SS*DK];
__device__ float g_v  [BB*HH*SS*DK];
__device__ float g_ctx[MM*DD];         // [B,S,D], tf32-grid
__device__ float g_tmp[MM*DD];         // attn_out, later ffn_out
__device__ float g_o1 [MM*DD];         // out1 (full precision, for residual)
__device__ float g_o1r[MM*DD];         // out1 rounded to tf32 grid (GEMM input)
__device__ float g_hid[(size_t)MM*FF]; // FFN hidden (tf32-grid, GEMM input)
__device__ float g_xr [MM*DD];         // x rounded to tf32 grid
__device__ float g_wr [12582912];      // all 6 weights rounded (48 MB)

// weight offsets inside g_wr (floats)
#define OFF_WQ 0
#define OFF_WK (OFF_WQ + DD*DD)
#define OFF_WV (OFF_WK + DD*DD)
#define OFF_WO (OFF_WV + DD*DD)
#define OFF_W1 (OFF_WO + DD*DD)
#define OFF_W2 (OFF_W1 + DD*FF)

// ---------------------------------------------------------------------------
// Helpers
// ---------------------------------------------------------------------------
__device__ __forceinline__ uint32_t f2tf32(float x) {
    uint32_t u;
    asm("cvt.rna.tf32.f32 %0, %1;" : "=r"(u) : "f"(x));
    return u;
}
__device__ __forceinline__ float tfr(float x) { return __uint_as_float(f2tf32(x)); }

__device__ __forceinline__ void mma8(float* c,
                                     uint32_t a0, uint32_t a1, uint32_t a2, uint32_t a3,
                                     uint32_t b0, uint32_t b1) {
    asm volatile(
        "mma.sync.aligned.m16n8k8.row.col.f32.tf32.tf32.f32 "
        "{%0,%1,%2,%3}, {%4,%5,%6,%7}, {%8,%9}, {%0,%1,%2,%3};\n"
        : "+f"(c[0]), "+f"(c[1]), "+f"(c[2]), "+f"(c[3])
        : "r"(a0), "r"(a1), "r"(a2), "r"(a3), "r"(b0), "r"(b1));
}

__device__ __forceinline__ void cpa16(uint32_t dst, const float* src) {
    asm volatile("cp.async.cg.shared.global [%0], [%1], 16;\n" :: "r"(dst), "l"(src));
}

__device__ __forceinline__ float gelu_erf(float x) {
    return 0.5f * x * (1.0f + erff(x * 0.70710678118654752440f));
}

// ---------------------------------------------------------------------------
// Elementwise tf32 rounding (run once per launch on x and weights)
// ---------------------------------------------------------------------------
__global__ void __launch_bounds__(256)
round_tf32_kernel(const float* __restrict__ src, float* __restrict__ dst, int n4)
{
    int i = blockIdx.x * 256 + threadIdx.x;
    if (i < n4) {
        float4 v = ((const float4*)src)[i];
        ((float4*)dst)[i] = make_float4(tfr(v.x), tfr(v.y), tfr(v.z), tfr(v.w));
    }
}

// ---------------------------------------------------------------------------
// TF32 GEMM, cp.async 4-stage pipeline.
// C[M,N] = A[M,K] @ W[K,N] + bias   (A and W MUST already be tf32-grid values)
//   EPI 0: plain store
//   EPI 1: GELU(erf), round to tf32 grid, store (feeds next GEMM)
//   EPI 2: scale by alpha, scatter into [B,H,S,dk]
// Tiles: BM=256, BN=128, BK=16; 256 threads = 8 warps (4x2), warp tile 64x64.
// smem: 4 stages x (256x20 + 16x136) floats = 114 KB (dynamic).
// ---------------------------------------------------------------------------
#define GSTAGES 4
#define SA_STRIDE 20
#define SB_STRIDE 136
#define SA_STAGE (256*SA_STRIDE)
#define SB_STAGE (16*SB_STRIDE)
#define GEMM_SMEM ((GSTAGES*(SA_STAGE + SB_STAGE)) * 4)

template <int EPI>
__global__ void __launch_bounds__(256)
gemm_cp(const float* __restrict__ A, const float* __restrict__ W,
        const float* __restrict__ bias, float* __restrict__ C,
        int M, int N, int K, float alpha)
{
    extern __shared__ float smem[];
    float* sA = smem;                       // [GSTAGES][256][20]
    float* sB = smem + GSTAGES * SA_STAGE;  // [GSTAGES][16][136]

    const int tid  = threadIdx.x;
    const int m0   = blockIdx.y * 256;
    const int n0   = blockIdx.x * 128;
    const int warp = tid >> 5, lane = tid & 31;
    const int g    = lane >> 2, tg = lane & 3;
    const int warpM = warp & 3;   // 0..3 -> 64-row group
    const int warpN = warp >> 2;  // 0..1 -> 64-col group

    const uint32_t sAu = (uint32_t)__cvta_generic_to_shared(sA);
    const uint32_t sBu = (uint32_t)__cvta_generic_to_shared(sB);

    // per-thread copy slots
    // A: 256x16 floats = 1024 float4 chunks -> 4 per thread
    // B: 16x128 floats =  512 float4 chunks -> 2 per thread
    int rA[4], cA[4], rBr[2], cBr[2];
#pragma unroll
    for (int i = 0; i < 4; i++) {
        int s = tid + i * 256;
        rA[i] = s >> 2; cA[i] = (s & 3) * 4;
    }
#pragma unroll
    for (int i = 0; i < 2; i++) {
        int s = tid + i * 256;
        rBr[i] = s >> 5; cBr[i] = (s & 31) * 4;
    }

    float acc[4][8][4];
#pragma unroll
    for (int a = 0; a < 4; a++)
#pragma unroll
        for (int b = 0; b < 8; b++)
#pragma unroll
            for (int c = 0; c < 4; c++) acc[a][b][c] = 0.f;

    const int nT = K / 16;

    // ---- issue helper (stage st, k offset k0) ----
    auto issue = [&](int st, int k0) {
#pragma unroll
        for (int i = 0; i < 4; i++)
            cpa16(sAu + (uint32_t)((st * SA_STAGE + rA[i] * SA_STRIDE + cA[i]) * 4),
                  A + (size_t)(m0 + rA[i]) * K + k0 + cA[i]);
#pragma unroll
        for (int i = 0; i < 2; i++)
            cpa16(sBu + (uint32_t)((st * SB_STAGE + rBr[i] * SB_STRIDE + cBr[i]) * 4),
                  W + (size_t)(k0 + rBr[i]) * N + n0 + cBr[i]);
        asm volatile("cp.async.commit_group;\n" ::: "memory");
    };

    // prologue: stages 0..2
    issue(0, 0);
    issue(1, 16);
    issue(2, 32);

    for (int t = 0; t < nT; t++) {
        if (t + 3 < nT) asm volatile("cp.async.wait_group 2;\n" ::: "memory");
        else            asm volatile("cp.async.wait_group 0;\n" ::: "memory");
        __syncthreads();
        if (t + 3 < nT) issue((t + 3) & 3, (t + 3) * 16);

        const float* pA = sA + (t & 3) * SA_STAGE;
        const float* pB = sB + (t & 3) * SB_STAGE;
#pragma unroll
        for (int ks = 0; ks < 2; ks++) {
            uint32_t af[4][4];
#pragma unroll
            for (int mf = 0; mf < 4; mf++) {
                int r = warpM * 64 + mf * 16 + g;
                int c = ks * 8 + tg;
                af[mf][0] = __float_as_uint(pA[r * SA_STRIDE + c]);
                af[mf][1] = __float_as_uint(pA[(r + 8) * SA_STRIDE + c]);
                af[mf][2] = __float_as_uint(pA[r * SA_STRIDE + c + 4]);
                af[mf][3] = __float_as_uint(pA[(r + 8) * SA_STRIDE + c + 4]);
            }
#pragma unroll
            for (int nf = 0; nf < 8; nf++) {
                int n  = warpN * 64 + nf * 8 + g;
                int kk = ks * 8 + tg;
                uint32_t b0 = __float_as_uint(pB[kk * SB_STRIDE + n]);
                uint32_t b1 = __float_as_uint(pB[(kk + 4) * SB_STRIDE + n]);
#pragma unroll
                for (int mf = 0; mf < 4; mf++)
                    mma8(acc[mf][nf], af[mf][0], af[mf][1], af[mf][2], af[mf][3], b0, b1);
            }
        }
    }

    // ---- epilogue ----
#pragma unroll
    for (int mf = 0; mf < 4; mf++) {
#pragma unroll
        for (int nf = 0; nf < 8; nf++) {
            int row = m0 + warpM * 64 + mf * 16 + g;
            int col = n0 + warpN * 64 + nf * 8 + tg * 2;
            float b0 = bias[col], b1 = bias[col + 1];
            float v0 = acc[mf][nf][0] + b0;
            float v1 = acc[mf][nf][1] + b1;
            float v2 = acc[mf][nf][2] + b0;
            float v3 = acc[mf][nf][3] + b1;
            if (EPI == 1) {
                v0 = tfr(gelu_erf(v0)); v1 = tfr(gelu_erf(v1));
                v2 = tfr(gelu_erf(v2)); v3 = tfr(gelu_erf(v3));
            }
            if (EPI == 2) {
                v0 *= alpha; v1 *= alpha; v2 *= alpha; v3 *= alpha;
                // (row,col) -> [B,H,S,dk]; 256-row tiles never cross a batch boundary
                int bI = row >> 9, s = row & 511;
                int h  = col >> 6, d = col & 63;
                size_t base = (((size_t)(bI * HH + h)) * SS + s) * DK + d;
                C[base]     = v0;
                C[base + 1] = v1;
                C[base + 8 * DK]     = v2;   // row+8 -> s+8 -> +8*DK
                C[base + 8 * DK + 1] = v3;
            } else {
                size_t p0 = (size_t)row * N + col;
                C[p0]     = v0;
                C[p0 + 1] = v1;
                C[p0 + (size_t)8 * N]     = v2;
                C[p0 + (size_t)8 * N + 1] = v3;
            }
        }
    }
}

// ---------------------------------------------------------------------------
// Attention: one CTA per (b, h, 64-row q tile). Full scores row (S=512) in
// dynamic smem -> exact two-phase softmax, then P@V. TF32 mma throughout.
// ctx is stored tf32-rounded (it feeds the Wo GEMM's cp.async path).
// ---------------------------------------------------------------------------
#define SS_STRIDE 516   // 516 % 32 == 4  -> banks (4q + c): conflict-free
#define SQ_STRIDE 68    //  68 % 32 == 4
#define SV_STRIDE 72    //  72 % 32 == 8  -> banks (8k + n): conflict-free
#define ATTN_SMEM ((64*SS_STRIDE + 64*SQ_STRIDE + 64*SV_STRIDE) * 4)

__global__ void __launch_bounds__(256)
attn_kernel(const float* __restrict__ adj, const int* __restrict__ mask)
{
    extern __shared__ float sm[];
    float* sS  = sm;                       // 64 x 516
    float* sQ  = sS + 64 * SS_STRIDE;      // 64 x 68
    float* sKV = sQ + 64 * SQ_STRIDE;      // 64 x 72 (K stride 68, V stride 72)
    __shared__ float sMaskB[SS];

    const int qt = blockIdx.x, h = blockIdx.y, b = blockIdx.z;
    const int q0 = qt * 64;
    const int tid = threadIdx.x;
    const int warp = tid >> 5, lane = tid & 31;
    const int g = lane >> 2, tg = lane & 3;

    const size_t headBase = ((size_t)(b * HH + h)) * SS * DK;

    for (int i = tid; i < SS; i += 256)
        sMaskB[i] = -1e9f * (float)mask[b * SS + i];

#pragma unroll
    for (int i = 0; i < 4; i++) {
        int s = tid + i * 256;
        int r = s >> 4, c = (s & 15) * 4;
        float4 v = *(const float4*)(g_q + headBase + (size_t)(q0 + r) * DK + c);
        *(float4*)&sQ[r * SQ_STRIDE + c] = make_float4(tfr(v.x), tfr(v.y), tfr(v.z), tfr(v.w));
    }
    __syncthreads();

    // ---- phase 1: scores = Q K^T + maskbias + adj ----
    {
        const int warpQ = warp & 1;
        const int warpK = warp >> 1;
        for (int ch = 0; ch < 8; ch++) {
#pragma unroll
            for (int i = 0; i < 4; i++) {
                int s = tid + i * 256;
                int r = s >> 4, c = (s & 15) * 4;
                float4 v = *(const float4*)(g_k + headBase + (size_t)(ch * 64 + r) * DK + c);
                *(float4*)&sKV[r * SQ_STRIDE + c] = make_float4(tfr(v.x), tfr(v.y), tfr(v.z), tfr(v.w));
            }
            __syncthreads();

            float acc[2][2][4];
#pragma unroll
            for (int a = 0; a < 2; a++)
#pragma unroll
                for (int n = 0; n < 2; n++)
#pragma unroll
                    for (int c = 0; c < 4; c++) acc[a][n][c] = 0.f;

#pragma unroll
            for (int ks = 0; ks < 8; ks++) {
                uint32_t af[2][4];
#pragma unroll
                for (int mf = 0; mf < 2; mf++) {
                    int r = warpQ * 32 + mf * 16 + g;
                    int c = ks * 8 + tg;
                    af[mf][0] = __float_as_uint(sQ[r * SQ_STRIDE + c]);
                    af[mf][1] = __float_as_uint(sQ[(r + 8) * SQ_STRIDE + c]);
                    af[mf][2] = __float_as_uint(sQ[r * SQ_STRIDE + c + 4]);
                    af[mf][3] = __float_as_uint(sQ[(r + 8) * SQ_STRIDE + c + 4]);
                }
#pragma unroll
                for (int nf = 0; nf < 2; nf++) {
                    int n  = warpK * 16 + nf * 8 + g;
                    int kk = ks * 8 + tg;
                    uint32_t b0 = __float_as_uint(sKV[n * SQ_STRIDE + kk]);
                    uint32_t b1 = __float_as_uint(sKV[n * SQ_STRIDE + kk + 4]);
                    mma8(acc[0][nf], af[0][0], af[0][1], af[0][2], af[0][3], b0, b1);
                    mma8(acc[1][nf], af[1][0], af[1][1], af[1][2], af[1][3], b0, b1);
                }
            }
#pragma unroll
            for (int mf = 0; mf < 2; mf++) {
#pragma unroll
                for (int nf = 0; nf < 2; nf++) {
                    int row = warpQ * 32 + mf * 16 + g;
                    int col = ch * 64 + warpK * 16 + nf * 8 + tg * 2;
                    const float* adj0 = adj + ((size_t)b * SS + q0 + row) * SS;
                    const float* adj1 = adj0 + 8 * SS;
                    sS[row * SS_STRIDE + col]           = acc[mf][nf][0] + sMaskB[col]     + adj0[col];
                    sS[row * SS_STRIDE + col + 1]       = acc[mf][nf][1] + sMaskB[col + 1] + adj0[col + 1];
                    sS[(row + 8) * SS_STRIDE + col]     = acc[mf][nf][2] + sMaskB[col]     + adj1[col];
                    sS[(row + 8) * SS_STRIDE + col + 1] = acc[mf][nf][3] + sMaskB[col + 1] + adj1[col + 1];
                }
            }
            __syncthreads();
        }
    }

    // ---- phase 2: softmax, each warp owns 8 rows ----
    {
        for (int r8 = 0; r8 < 8; r8++) {
            float* Sr = sS + (warp * 8 + r8) * SS_STRIDE;
            float mx = -3.4e38f;
            for (int j = lane; j < SS; j += 32) mx = fmaxf(mx, Sr[j]);
#pragma unroll
            for (int o = 16; o; o >>= 1) mx = fmaxf(mx, __shfl_xor_sync(0xffffffffu, mx, o));
            float sum = 0.f;
            for (int j = lane; j < SS; j += 32) {
                float e = __expf(Sr[j] - mx);
                Sr[j] = e;
                sum += e;
            }
#pragma unroll
            for (int o = 16; o; o >>= 1) sum += __shfl_xor_sync(0xffffffffu, sum, o);
            float inv = 1.f / sum;
            for (int j = lane; j < SS; j += 32) Sr[j] = tfr(Sr[j] * inv);
        }
        __syncthreads();
    }

    // ---- phase 3: ctx = P @ V ----
    {
        const int warpQ = warp & 1;
        const int warpD = warp >> 1;
        float o[2][2][4];
#pragma unroll
        for (int a = 0; a < 2; a++)
#pragma unroll
            for (int n = 0; n < 2; n++)
#pragma unroll
                for (int c = 0; c < 4; c++) o[a][n][c] = 0.f;

        for (int ch = 0; ch < 8; ch++) {
#pragma unroll
            for (int i = 0; i < 4; i++) {
                int s = tid + i * 256;
                int r = s >> 4, c = (s & 15) * 4;
                float4 v = *(const float4*)(g_v + headBase + (size_t)(ch * 64 + r) * DK + c);
                *(float4*)&sKV[r * SV_STRIDE + c] = make_float4(tfr(v.x), tfr(v.y), tfr(v.z), tfr(v.w));
            }
            __syncthreads();

#pragma unroll
            for (int ks = 0; ks < 8; ks++) {
                uint32_t af[2][4];
#pragma unroll
                for (int mf = 0; mf < 2; mf++) {
                    int r = warpQ * 32 + mf * 16 + g;
                    int c = ch * 64 + ks * 8 + tg;
                    af[mf][0] = __float_as_uint(sS[r * SS_STRIDE + c]);
                    af[mf][1] = __float_as_uint(sS[(r + 8) * SS_STRIDE + c]);
                    af[mf][2] = __float_as_uint(sS[r * SS_STRIDE + c + 4]);
                    af[mf][3] = __float_as_uint(sS[(r + 8) * SS_STRIDE + c + 4]);
                }
#pragma unroll
                for (int nf = 0; nf < 2; nf++) {
                    int n  = warpD * 16 + nf * 8 + g;
                    int kk = ks * 8 + tg;
                    uint32_t b0 = __float_as_uint(sKV[kk * SV_STRIDE + n]);
                    uint32_t b1 = __float_as_uint(sKV[(kk + 4) * SV_STRIDE + n]);
                    mma8(o[0][nf], af[0][0], af[0][1], af[0][2], af[0][3], b0, b1);
                    mma8(o[1][nf], af[1][0], af[1][1], af[1][2], af[1][3], b0, b1);
                }
            }
            __syncthreads();
        }

        // write ctx (tf32-rounded: feeds Wo GEMM cp.async path)
#pragma unroll
        for (int mf = 0; mf < 2; mf++) {
#pragma unroll
            for (int nf = 0; nf < 2; nf++) {
                int q = q0 + warpQ * 32 + mf * 16 + g;
                int d = warpD * 16 + nf * 8 + tg * 2;
                size_t base = ((size_t)b * SS + q) * DD + h * DK + d;
                g_ctx[base]     = tfr(o[mf][nf][0]);
                g_ctx[base + 1] = tfr(o[mf][nf][1]);
                g_ctx[base + 8 * DD]     = tfr(o[mf][nf][2]);
                g_ctx[base + 8 * DD + 1] = tfr(o[mf][nf][3]);
            }
        }
    }
}

// ---------------------------------------------------------------------------
// Residual + LayerNorm (torch semantics: unbiased std, / (std + eps)).
// Optionally also writes a tf32-rounded copy (for the next GEMM's A input).
// ---------------------------------------------------------------------------
__global__ void __launch_bounds__(256)
ln_kernel(const float* __restrict__ a, const float* __restrict__ r,
          const float* __restrict__ gamma, const float* __restrict__ beta,
          float* __restrict__ out, float* __restrict__ out_r)
{
    __shared__ float red[8];
    const int row = blockIdx.x;
    const int tid = threadIdx.x;
    const int warp = tid >> 5, lane = tid & 31;

    float4 va = ((const float4*)(a + (size_t)row * DD))[tid];
    float4 vr = ((const float4*)(r + (size_t)row * DD))[tid];
    float v0 = va.x + vr.x, v1 = va.y + vr.y, v2 = va.z + vr.z, v3 = va.w + vr.w;

    float s = v0 + v1 + v2 + v3;
#pragma unroll
    for (int o = 16; o; o >>= 1) s += __shfl_xor_sync(0xffffffffu, s, o);
    if (lane == 0) red[warp] = s;
    __syncthreads();
    float tot = 0.f;
#pragma unroll
    for (int i = 0; i < 8; i++) tot += red[i];
    float mean = tot * (1.0f / 1024.0f);
    __syncthreads();

    float d0 = v0 - mean, d1 = v1 - mean, d2 = v2 - mean, d3 = v3 - mean;
    float sq = d0 * d0 + d1 * d1 + d2 * d2 + d3 * d3;
#pragma unroll
    for (int o = 16; o; o >>= 1) sq += __shfl_xor_sync(0xffffffffu, sq, o);
    if (lane == 0) red[warp] = sq;
    __syncthreads();
    float tot2 = 0.f;
#pragma unroll
    for (int i = 0; i < 8; i++) tot2 += red[i];
    float var = tot2 * (1.0f / 1023.0f);        // ddof=1
    float inv = 1.0f / (sqrtf(var) + 1e-6f);     // (std + eps)

    float4 gm = ((const float4*)gamma)[tid];
    float4 bt = ((const float4*)beta)[tid];
    float4 o4;
    o4.x = gm.x * d0 * inv + bt.x;
    o4.y = gm.y * d1 * inv + bt.y;
    o4.z = gm.z * d2 * inv + bt.z;
    o4.w = gm.w * d3 * inv + bt.w;
    ((float4*)(out + (size_t)row * DD))[tid] = o4;
    if (out_r)
        ((float4*)(out_r + (size_t)row * DD))[tid] =
            make_float4(tfr(o4.x), tfr(o4.y), tfr(o4.z), tfr(o4.w));
}

// ---------------------------------------------------------------------------
// Launch
// ---------------------------------------------------------------------------
extern "C" void kernel_launch(void* const* d_in, const int* in_sizes, int n_in,
                              void* d_out, int out_size)
{
    const float* x    = (const float*)d_in[0];
    const int*   mask = (const int*)  d_in[1];
    const float* adj  = (const float*)d_in[2];
    int base = (n_in > 3 && in_sizes[3] == 1) ? 4 : 3;
    const float* Wq = (const float*)d_in[base + 0];
    const float* bq = (const float*)d_in[base + 1];
    const float* Wk = (const float*)d_in[base + 2];
    const float* bk = (const float*)d_in[base + 3];
    const float* Wv = (const float*)d_in[base + 4];
    const float* bv = (const float*)d_in[base + 5];
    const float* Wo = (const float*)d_in[base + 6];
    const float* bo = (const float*)d_in[base + 7];
    const float* W1 = (const float*)d_in[base + 8];
    const float* b1 = (const float*)d_in[base + 9];
    const float* W2 = (const float*)d_in[base + 10];
    const float* b2 = (const float*)d_in[base + 11];
    const float* gm = (const float*)d_in[base + 12];
    const float* bt = (const float*)d_in[base + 13];
    float* out = (float*)d_out;

    float *q, *k, *v, *ctx, *tmp, *o1, *o1r, *hid, *xr, *wr;
    cudaGetSymbolAddress((void**)&q,   g_q);
    cudaGetSymbolAddress((void**)&k,   g_k);
    cudaGetSymbolAddress((void**)&v,   g_v);
    cudaGetSymbolAddress((void**)&ctx, g_ctx);
    cudaGetSymbolAddress((void**)&tmp, g_tmp);
    cudaGetSymbolAddress((void**)&o1,  g_o1);
    cudaGetSymbolAddress((void**)&o1r, g_o1r);
    cudaGetSymbolAddress((void**)&hid, g_hid);
    cudaGetSymbolAddress((void**)&xr,  g_xr);
    cudaGetSymbolAddress((void**)&wr,  g_wr);

    cudaFuncSetAttribute(gemm_cp<0>, cudaFuncAttributeMaxDynamicSharedMemorySize, GEMM_SMEM);
    cudaFuncSetAttribute(gemm_cp<1>, cudaFuncAttributeMaxDynamicSharedMemorySize, GEMM_SMEM);
    cudaFuncSetAttribute(gemm_cp<2>, cudaFuncAttributeMaxDynamicSharedMemorySize, GEMM_SMEM);
    cudaFuncSetAttribute(attn_kernel, cudaFuncAttributeMaxDynamicSharedMemorySize, ATTN_SMEM);

    // ---- pre-round x and all weights to the tf32 grid ----
    {
        int n4;
        n4 = MM * DD / 4;   round_tf32_kernel<<<(n4 + 255) / 256, 256>>>(x,  xr, n4);
        n4 = DD * DD / 4;
        round_tf32_kernel<<<(n4 + 255) / 256, 256>>>(Wq, wr + OFF_WQ, n4);
        round_tf32_kernel<<<(n4 + 255) / 256, 256>>>(Wk, wr + OFF_WK, n4);
        round_tf32_kernel<<<(n4 + 255) / 256, 256>>>(Wv, wr + OFF_WV, n4);
        round_tf32_kernel<<<(n4 + 255) / 256, 256>>>(Wo, wr + OFF_WO, n4);
        n4 = DD * FF / 4;
        round_tf32_kernel<<<(n4 + 255) / 256, 256>>>(W1, wr + OFF_W1, n4);
        round_tf32_kernel<<<(n4 + 255) / 256, 256>>>(W2, wr + OFF_W2, n4);
    }

    dim3 gD(DD / 128, MM / 256);   // (8, 64)
    dim3 gF(FF / 128, MM / 256);   // (32, 64)

    // QKV projections (Q pre-scaled by 1/sqrt(64) = 0.125)
    gemm_cp<2><<<gD, 256, GEMM_SMEM>>>(xr, wr + OFF_WQ, bq, q, MM, DD, DD, 0.125f);
    gemm_cp<2><<<gD, 256, GEMM_SMEM>>>(xr, wr + OFF_WK, bk, k, MM, DD, DD, 1.0f);
    gemm_cp<2><<<gD, 256, GEMM_SMEM>>>(xr, wr + OFF_WV, bv, v, MM, DD, DD, 1.0f);

    attn_kernel<<<dim3(SS / 64, HH, BB), 256, ATTN_SMEM>>>(adj, mask);

    gemm_cp<0><<<gD, 256, GEMM_SMEM>>>(ctx, wr + OFF_WO, bo, tmp, MM, DD, DD, 1.0f);
    ln_kernel<<<MM, 256>>>(x, tmp, gm, bt, o1, o1r);

    gemm_cp<1><<<gF, 256, GEMM_SMEM>>>(o1r, wr + OFF_W1, b1, hid, MM, FF, DD, 1.0f);
    gemm_cp<0><<<gD, 256, GEMM_SMEM>>>(hid, wr + OFF_W2, b2, tmp, MM, DD, FF, 1.0f);
    ln_kernel<<<MM, 256>>>(o1, tmp, gm, bt, out, nullptr);
}

// round 13
// speedup vs baseline: 1.8478x; 1.8478x over previous
#include <cuda_runtime.h>
#include <cuda_fp16.h>
#include <cstdint>
#include <math.h>

// Problem dims (fixed by the reference)
#define BB 32
#define SS 512
#define DD 1024
#define HH 16
#define DK 64
#define FF 4096
#define MM (BB*SS)   // 16384 rows

// ---------------------------------------------------------------------------
// Scratch (static device arrays; no allocation APIs anywhere)
// ---------------------------------------------------------------------------
__device__ __half g_qh [BB*HH*SS*DK];   // [B,H,S,dk] fp16, Q pre-scaled by 1/8
__device__ __half g_kh [BB*HH*SS*DK];
__device__ __half g_vh [BB*HH*SS*DK];
__device__ __half g_ctxh[MM*DD];        // [B,S,D] fp16
__device__ float  g_tmp[MM*DD];         // attn_out / ffn_out (fp32)
__device__ float  g_o1 [MM*DD];         // out1 fp32 (residual)
__device__ __half g_o1h[MM*DD];         // out1 fp16 (GEMM input)
__device__ __half g_hidh[(size_t)MM*FF];// FFN hidden fp16
__device__ __half g_xh [MM*DD];         // x fp16
__device__ __half g_wt [12582912];      // all 6 weights fp16, TRANSPOSED [N,K]

#define OFF_WQ 0
#define OFF_WK (OFF_WQ + DD*DD)
#define OFF_WV (OFF_WK + DD*DD)
#define OFF_WO (OFF_WV + DD*DD)
#define OFF_W1 (OFF_WO + DD*DD)
#define OFF_W2 (OFF_W1 + DD*FF)

// ---------------------------------------------------------------------------
// Helpers
// ---------------------------------------------------------------------------
__device__ __forceinline__ void mma16(float* c, uint32_t a0, uint32_t a1,
                                      uint32_t a2, uint32_t a3,
                                      uint32_t b0, uint32_t b1) {
    asm volatile(
        "mma.sync.aligned.m16n8k16.row.col.f32.f16.f16.f32 "
        "{%0,%1,%2,%3}, {%4,%5,%6,%7}, {%8,%9}, {%0,%1,%2,%3};\n"
        : "+f"(c[0]), "+f"(c[1]), "+f"(c[2]), "+f"(c[3])
        : "r"(a0), "r"(a1), "r"(a2), "r"(a3), "r"(b0), "r"(b1));
}

__device__ __forceinline__ void cpa16(uint32_t dst, const void* src) {
    asm volatile("cp.async.cg.shared.global [%0], [%1], 16;\n" :: "r"(dst), "l"(src));
}

__device__ __forceinline__ void ldmx4t(uint32_t& r0, uint32_t& r1,
                                       uint32_t& r2, uint32_t& r3, uint32_t addr) {
    asm volatile(
        "ldmatrix.sync.aligned.m8n8.x4.trans.shared.b16 {%0,%1,%2,%3}, [%4];"
        : "=r"(r0), "=r"(r1), "=r"(r2), "=r"(r3) : "r"(addr));
}

__device__ __forceinline__ float gelu_erf(float x) {
    return 0.5f * x * (1.0f + erff(x * 0.70710678118654752440f));
}

__device__ __forceinline__ uint32_t ldh32(const __half* p) {
    return *(const uint32_t*)p;
}

// ---------------------------------------------------------------------------
// Preprocessing: fp32 -> fp16 convert; transpose+convert weights to [N,K]
// ---------------------------------------------------------------------------
__global__ void __launch_bounds__(256)
hconv_kernel(const float* __restrict__ src, __half* __restrict__ dst, int n4)
{
    int i = blockIdx.x * 256 + threadIdx.x;
    if (i < n4) {
        float4 v = ((const float4*)src)[i];
        __half2 a = __floats2half2_rn(v.x, v.y);
        __half2 b = __floats2half2_rn(v.z, v.w);
        ((__half2*)dst)[i*2]   = a;
        ((__half2*)dst)[i*2+1] = b;
    }
}

__global__ void __launch_bounds__(256)
wtrans_kernel(const float* __restrict__ W, __half* __restrict__ Wt, int K, int N)
{
    __shared__ float t[32][33];
    int n0 = blockIdx.x * 32, k0 = blockIdx.y * 32;
    int tx = threadIdx.x & 31, ty = threadIdx.x >> 5;  // 32x8
#pragma unroll
    for (int j = 0; j < 4; j++)
        t[ty + j*8][tx] = W[(size_t)(k0 + ty + j*8) * N + n0 + tx];
    __syncthreads();
#pragma unroll
    for (int j = 0; j < 4; j++)
        Wt[(size_t)(n0 + ty + j*8) * K + k0 + tx] = __float2half(t[tx][ty + j*8]);
}

// ---------------------------------------------------------------------------
// FP16 GEMM: C[M,N] = A[M,K] @ Wt[N,K]^T + bias
//   EPI 0: fp32 store
//   EPI 1: GELU -> fp16 store (hidden)
//   EPI 2: alpha-scale -> fp16 scatter into [B,H,S,dk]
// BM=128, BN=128, BK=32; 256 threads = 8 warps (2x4), warp tile 64x32.
// 4-stage cp.async; smem stride 40 halves (80B) - bank-clean for STS.128
// quarter-warp phases and for all 32-bit fragment LDS patterns.
// ---------------------------------------------------------------------------
#define HST 40                 // halves per smem row
#define STG_H (256*HST)        // halves per stage (A 128 rows + B 128 rows)
#define GEMM_SMEM (4*STG_H*2)  // bytes = 4 stages * 10240 halves * 2

template <int EPI>
__global__ void __launch_bounds__(256)
gemm_h(const __half* __restrict__ A, const __half* __restrict__ Bt,
       const float* __restrict__ bias,
       float* __restrict__ Cf, __half* __restrict__ Ch,
       int M, int N, int K, float alpha)
{
    extern __shared__ __half hsm[];
    const uint32_t sb = (uint32_t)__cvta_generic_to_shared(hsm);

    const int tid  = threadIdx.x;
    const int m0   = blockIdx.y * 128;
    const int n0   = blockIdx.x * 128;
    const int warp = tid >> 5, lane = tid & 31;
    const int g    = lane >> 2, tg = lane & 3;
    const int warpM = warp & 1;   // 0..1 -> 64-row group
    const int warpN = warp >> 1;  // 0..3 -> 32-col group

    // cp.async slot mapping: conflict-free STS.128 quarter-warp phases
    const int rlow = tid & 7, qc = (tid >> 3) & 3, w8 = tid >> 5;

    float acc[4][4][4];
#pragma unroll
    for (int a = 0; a < 4; a++)
#pragma unroll
        for (int b = 0; b < 4; b++)
#pragma unroll
            for (int c = 0; c < 4; c++) acc[a][b][c] = 0.f;

    const int nT = K / 32;

    auto issue = [&](int st, int c) {
        const int k0 = c * 32;
        const uint32_t base = sb + st * (STG_H * 2);
#pragma unroll
        for (int it = 0; it < 2; it++) {
            int r = rlow + 8 * w8 + 64 * it;
            cpa16(base + (uint32_t)(r * 80 + qc * 16),
                  A + (size_t)(m0 + r) * K + k0 + qc * 8);
            cpa16(base + (uint32_t)(128 * 80 + r * 80 + qc * 16),
                  Bt + (size_t)(n0 + r) * K + k0 + qc * 8);
        }
        asm volatile("cp.async.commit_group;\n" ::: "memory");
    };

    issue(0, 0);
    issue(1, 1);
    issue(2, 2);

    for (int t = 0; t < nT; t++) {
        if (t + 3 < nT) asm volatile("cp.async.wait_group 2;\n" ::: "memory");
        else            asm volatile("cp.async.wait_group 0;\n" ::: "memory");
        __syncthreads();
        if (t + 3 < nT) issue((t + 3) & 3, t + 3);

        const __half* pA = hsm + (t & 3) * STG_H;
        const __half* pB = pA + 128 * HST;
#pragma unroll
        for (int ks = 0; ks < 2; ks++) {
            uint32_t af[4][4];
#pragma unroll
            for (int mf = 0; mf < 4; mf++) {
                int r = warpM * 64 + mf * 16 + g;
                int c = ks * 16 + 2 * tg;
                af[mf][0] = ldh32(pA + r * HST + c);
                af[mf][1] = ldh32(pA + (r + 8) * HST + c);
                af[mf][2] = ldh32(pA + r * HST + c + 8);
                af[mf][3] = ldh32(pA + (r + 8) * HST + c + 8);
            }
#pragma unroll
            for (int nf = 0; nf < 4; nf++) {
                int n = warpN * 32 + nf * 8 + g;
                int c = ks * 16 + 2 * tg;
                uint32_t b0 = ldh32(pB + n * HST + c);
                uint32_t b1 = ldh32(pB + n * HST + c + 8);
#pragma unroll
                for (int mf = 0; mf < 4; mf++)
                    mma16(acc[mf][nf], af[mf][0], af[mf][1], af[mf][2], af[mf][3], b0, b1);
            }
        }
    }

    // ---- epilogue ----
#pragma unroll
    for (int mf = 0; mf < 4; mf++) {
#pragma unroll
        for (int nf = 0; nf < 4; nf++) {
            int row = m0 + warpM * 64 + mf * 16 + g;
            int col = n0 + warpN * 32 + nf * 8 + 2 * tg;
            float b0 = bias[col], b1 = bias[col + 1];
            float v0 = acc[mf][nf][0] + b0;
            float v1 = acc[mf][nf][1] + b1;
            float v2 = acc[mf][nf][2] + b0;
            float v3 = acc[mf][nf][3] + b1;
            if (EPI == 0) {
                *(float2*)(Cf + (size_t)row * N + col)       = make_float2(v0, v1);
                *(float2*)(Cf + (size_t)(row + 8) * N + col) = make_float2(v2, v3);
            } else if (EPI == 1) {
                *(__half2*)(Ch + (size_t)row * N + col)       = __floats2half2_rn(gelu_erf(v0), gelu_erf(v1));
                *(__half2*)(Ch + (size_t)(row + 8) * N + col) = __floats2half2_rn(gelu_erf(v2), gelu_erf(v3));
            } else { // EPI == 2: scatter into [B,H,S,dk]
                int bI = row >> 9, s = row & 511;
                int h  = col >> 6, d = col & 63;
                size_t base = (((size_t)(bI * HH + h)) * SS + s) * DK + d;
                *(__half2*)(Ch + base)            = __floats2half2_rn(v0 * alpha, v1 * alpha);
                *(__half2*)(Ch + base + 8 * DK)   = __floats2half2_rn(v2 * alpha, v3 * alpha);
            }
        }
    }
}

// ---------------------------------------------------------------------------
// Attention: one CTA per (b, h, 64 q-rows). FP16 m16n8k16 for QK^T and PV;
// fp32 scores + exact softmax; P stored fp16; V frags via ldmatrix.trans.
// ---------------------------------------------------------------------------
#define SSF_STRIDE 516   // fp32 scores row stride
#define SQH_STRIDE 72    // Q/K/V half tiles (stride 72 halves = 36 banks: clean)
#define SPH_STRIDE 520   // P half rows
#define AT_Q_OFF  (64*SSF_STRIDE*4)                  // 132096
#define AT_KV_OFF (AT_Q_OFF + 64*SQH_STRIDE*2)       // 141312
#define AT_P_OFF  (AT_KV_OFF + 64*SQH_STRIDE*2)      // 150528
#define ATTN_SMEM (AT_P_OFF + 64*SPH_STRIDE*2)       // 217088

__global__ void __launch_bounds__(256)
attn_kernel(const float* __restrict__ adj, const int* __restrict__ mask)
{
    extern __shared__ char smb[];
    float*  sS  = (float*)smb;
    __half* sQh = (__half*)(smb + AT_Q_OFF);
    __half* sKV = (__half*)(smb + AT_KV_OFF);
    __half* sP  = (__half*)(smb + AT_P_OFF);
    const uint32_t sbu = (uint32_t)__cvta_generic_to_shared(smb);
    __shared__ float sMaskB[SS];

    const int qt = blockIdx.x, h = blockIdx.y, b = blockIdx.z;
    const int q0 = qt * 64;
    const int tid = threadIdx.x;
    const int warp = tid >> 5, lane = tid & 31;
    const int g = lane >> 2, tg = lane & 3;

    const size_t headBase = ((size_t)(b * HH + h)) * SS * DK;

    for (int i = tid; i < SS; i += 256)
        sMaskB[i] = -1e9f * (float)mask[b * SS + i];

    // Q tile (fp16, pre-scaled by 1/8)
#pragma unroll
    for (int i = 0; i < 2; i++) {
        int s = tid + i * 256;
        int r = s >> 3, c8 = s & 7;
        *(uint4*)(sQh + r * SQH_STRIDE + c8 * 8) =
            *(const uint4*)(g_qh + headBase + (size_t)(q0 + r) * DK + c8 * 8);
    }
    __syncthreads();

    // ---- phase 1: scores = Q K^T + maskbias + adj ----
    {
        const int warpQ = warp & 1;   // 32 q-rows
        const int warpK = warp >> 1;  // 16 keys
        for (int ch = 0; ch < 8; ch++) {
#pragma unroll
            for (int i = 0; i < 2; i++) {
                int s = tid + i * 256;
                int r = s >> 3, c8 = s & 7;
                *(uint4*)(sKV + r * SQH_STRIDE + c8 * 8) =
                    *(const uint4*)(g_kh + headBase + (size_t)(ch * 64 + r) * DK + c8 * 8);
            }
            __syncthreads();

            float acc[2][2][4];
#pragma unroll
            for (int a = 0; a < 2; a++)
#pragma unroll
                for (int n = 0; n < 2; n++)
#pragma unroll
                    for (int c = 0; c < 4; c++) acc[a][n][c] = 0.f;

#pragma unroll
            for (int ks = 0; ks < 4; ks++) {
                uint32_t af[2][4];
#pragma unroll
                for (int mf = 0; mf < 2; mf++) {
                    int r = warpQ * 32 + mf * 16 + g;
                    int c = ks * 16 + 2 * tg;
                    af[mf][0] = ldh32(sQh + r * SQH_STRIDE + c);
                    af[mf][1] = ldh32(sQh + (r + 8) * SQH_STRIDE + c);
                    af[mf][2] = ldh32(sQh + r * SQH_STRIDE + c + 8);
                    af[mf][3] = ldh32(sQh + (r + 8) * SQH_STRIDE + c + 8);
                }
#pragma unroll
                for (int nf = 0; nf < 2; nf++) {
                    int n = warpK * 16 + nf * 8 + g;
                    int c = ks * 16 + 2 * tg;
                    uint32_t b0 = ldh32(sKV + n * SQH_STRIDE + c);
                    uint32_t b1 = ldh32(sKV + n * SQH_STRIDE + c + 8);
                    mma16(acc[0][nf], af[0][0], af[0][1], af[0][2], af[0][3], b0, b1);
                    mma16(acc[1][nf], af[1][0], af[1][1], af[1][2], af[1][3], b0, b1);
                }
            }
#pragma unroll
            for (int mf = 0; mf < 2; mf++) {
#pragma unroll
                for (int nf = 0; nf < 2; nf++) {
                    int row = warpQ * 32 + mf * 16 + g;
                    int col = ch * 64 + warpK * 16 + nf * 8 + 2 * tg;
                    const float* adj0 = adj + ((size_t)b * SS + q0 + row) * SS;
                    const float* adj1 = adj0 + 8 * SS;
                    sS[row * SSF_STRIDE + col]           = acc[mf][nf][0] + sMaskB[col]     + adj0[col];
                    sS[row * SSF_STRIDE + col + 1]       = acc[mf][nf][1] + sMaskB[col + 1] + adj0[col + 1];
                    sS[(row + 8) * SSF_STRIDE + col]     = acc[mf][nf][2] + sMaskB[col]     + adj1[col];
                    sS[(row + 8) * SSF_STRIDE + col + 1] = acc[mf][nf][3] + sMaskB[col + 1] + adj1[col + 1];
                }
            }
            __syncthreads();
        }
    }

    // ---- phase 2: softmax (fp32), emit P as fp16 ----
    {
        for (int r8 = 0; r8 < 8; r8++) {
            const int row = warp * 8 + r8;
            const float* Sr = sS + row * SSF_STRIDE;
            float2 v[8];
            float mx = -3.4e38f;
#pragma unroll
            for (int i = 0; i < 8; i++) {
                v[i] = *(const float2*)(Sr + 2 * lane + 64 * i);
                mx = fmaxf(mx, fmaxf(v[i].x, v[i].y));
            }
#pragma unroll
            for (int o = 16; o; o >>= 1) mx = fmaxf(mx, __shfl_xor_sync(0xffffffffu, mx, o));
            float sum = 0.f;
#pragma unroll
            for (int i = 0; i < 8; i++) {
                v[i].x = __expf(v[i].x - mx);
                v[i].y = __expf(v[i].y - mx);
                sum += v[i].x + v[i].y;
            }
#pragma unroll
            for (int o = 16; o; o >>= 1) sum += __shfl_xor_sync(0xffffffffu, sum, o);
            float inv = 1.f / sum;
            __half* Pr = sP + row * SPH_STRIDE;
#pragma unroll
            for (int i = 0; i < 8; i++)
                *(__half2*)(Pr + 2 * lane + 64 * i) = __floats2half2_rn(v[i].x * inv, v[i].y * inv);
        }
        __syncthreads();
    }

    // ---- phase 3: ctx = P @ V ----
    {
        const int warpQ = warp & 1;
        const int warpD = warp >> 1;   // 16 dims
        float o[2][2][4];
#pragma unroll
        for (int a = 0; a < 2; a++)
#pragma unroll
            for (int n = 0; n < 2; n++)
#pragma unroll
                for (int c = 0; c < 4; c++) o[a][n][c] = 0.f;

        for (int ch = 0; ch < 8; ch++) {
#pragma unroll
            for (int i = 0; i < 2; i++) {
                int s = tid + i * 256;
                int r = s >> 3, c8 = s & 7;
                *(uint4*)(sKV + r * SQH_STRIDE + c8 * 8) =
                    *(const uint4*)(g_vh + headBase + (size_t)(ch * 64 + r) * DK + c8 * 8);
            }
            __syncthreads();

#pragma unroll
            for (int ks = 0; ks < 4; ks++) {
                uint32_t af[2][4];
#pragma unroll
                for (int mf = 0; mf < 2; mf++) {
                    int r = warpQ * 32 + mf * 16 + g;
                    int c = ch * 64 + ks * 16 + 2 * tg;
                    af[mf][0] = ldh32(sP + r * SPH_STRIDE + c);
                    af[mf][1] = ldh32(sP + (r + 8) * SPH_STRIDE + c);
                    af[mf][2] = ldh32(sP + r * SPH_STRIDE + c + 8);
                    af[mf][3] = ldh32(sP + (r + 8) * SPH_STRIDE + c + 8);
                }
                // V fragments via ldmatrix.x4.trans (row-major [key][dim])
                uint32_t bv[4];
                {
                    int key = ks * 16 + (lane & 7) + (lane & 8);
                    int dmc = warpD * 16 + ((lane >> 4) << 3);
                    uint32_t addr = sbu + AT_KV_OFF
                                  + (uint32_t)(key * SQH_STRIDE + dmc) * 2u;
                    ldmx4t(bv[0], bv[1], bv[2], bv[3], addr);
                }
#pragma unroll
                for (int nb = 0; nb < 2; nb++) {
                    mma16(o[0][nb], af[0][0], af[0][1], af[0][2], af[0][3], bv[nb*2], bv[nb*2+1]);
                    mma16(o[1][nb], af[1][0], af[1][1], af[1][2], af[1][3], bv[nb*2], bv[nb*2+1]);
                }
            }
            __syncthreads();
        }

        // ctx fp16 in [B,S,D] (D index = h*64 + d)
#pragma unroll
        for (int mf = 0; mf < 2; mf++) {
#pragma unroll
            for (int nb = 0; nb < 2; nb++) {
                int q = q0 + warpQ * 32 + mf * 16 + g;
                int d = warpD * 16 + nb * 8 + 2 * tg;
                size_t base = ((size_t)b * SS + q) * DD + h * DK + d;
                *(__half2*)(g_ctxh + base)          = __floats2half2_rn(o[mf][nb][0], o[mf][nb][1]);
                *(__half2*)(g_ctxh + base + 8 * DD) = __floats2half2_rn(o[mf][nb][2], o[mf][nb][3]);
            }
        }
    }
}

// ---------------------------------------------------------------------------
// Residual + LayerNorm (torch semantics: unbiased std, / (std + eps)).
// Optionally also emits an fp16 copy for the next GEMM.
// ---------------------------------------------------------------------------
__global__ void __launch_bounds__(256)
ln_kernel(const float* __restrict__ a, const float* __restrict__ r,
          const float* __restrict__ gamma, const float* __restrict__ beta,
          float* __restrict__ out, __half* __restrict__ oh)
{
    __shared__ float red[8];
    const int row = blockIdx.x;
    const int tid = threadIdx.x;
    const int warp = tid >> 5, lane = tid & 31;

    float4 va = ((const float4*)(a + (size_t)row * DD))[tid];
    float4 vr = ((const float4*)(r + (size_t)row * DD))[tid];
    float v0 = va.x + vr.x, v1 = va.y + vr.y, v2 = va.z + vr.z, v3 = va.w + vr.w;

    float s = v0 + v1 + v2 + v3;
#pragma unroll
    for (int o = 16; o; o >>= 1) s += __shfl_xor_sync(0xffffffffu, s, o);
    if (lane == 0) red[warp] = s;
    __syncthreads();
    float tot = 0.f;
#pragma unroll
    for (int i = 0; i < 8; i++) tot += red[i];
    float mean = tot * (1.0f / 1024.0f);
    __syncthreads();

    float d0 = v0 - mean, d1 = v1 - mean, d2 = v2 - mean, d3 = v3 - mean;
    float sq = d0 * d0 + d1 * d1 + d2 * d2 + d3 * d3;
#pragma unroll
    for (int o = 16; o; o >>= 1) sq += __shfl_xor_sync(0xffffffffu, sq, o);
    if (lane == 0) red[warp] = sq;
    __syncthreads();
    float tot2 = 0.f;
#pragma unroll
    for (int i = 0; i < 8; i++) tot2 += red[i];
    float var = tot2 * (1.0f / 1023.0f);         // ddof=1
    float inv = 1.0f / (sqrtf(var) + 1e-6f);      // (std + eps)

    float4 gm = ((const float4*)gamma)[tid];
    float4 bt = ((const float4*)beta)[tid];
    float4 o4;
    o4.x = gm.x * d0 * inv + bt.x;
    o4.y = gm.y * d1 * inv + bt.y;
    o4.z = gm.z * d2 * inv + bt.z;
    o4.w = gm.w * d3 * inv + bt.w;
    ((float4*)(out + (size_t)row * DD))[tid] = o4;
    if (oh) {
        size_t o = (size_t)row * DD + tid * 4;
        *(__half2*)(oh + o)     = __floats2half2_rn(o4.x, o4.y);
        *(__half2*)(oh + o + 2) = __floats2half2_rn(o4.z, o4.w);
    }
}

// ---------------------------------------------------------------------------
// Launch
// ---------------------------------------------------------------------------
extern "C" void kernel_launch(void* const* d_in, const int* in_sizes, int n_in,
                              void* d_out, int out_size)
{
    const float* x    = (const float*)d_in[0];
    const int*   mask = (const int*)  d_in[1];
    const float* adj  = (const float*)d_in[2];
    int base = (n_in > 3 && in_sizes[3] == 1) ? 4 : 3;
    const float* Wq = (const float*)d_in[base + 0];
    const float* bq = (const float*)d_in[base + 1];
    const float* Wk = (const float*)d_in[base + 2];
    const float* bk = (const float*)d_in[base + 3];
    const float* Wv = (const float*)d_in[base + 4];
    const float* bv = (const float*)d_in[base + 5];
    const float* Wo = (const float*)d_in[base + 6];
    const float* bo = (const float*)d_in[base + 7];
    const float* W1 = (const float*)d_in[base + 8];
    const float* b1 = (const float*)d_in[base + 9];
    const float* W2 = (const float*)d_in[base + 10];
    const float* b2 = (const float*)d_in[base + 11];
    const float* gm = (const float*)d_in[base + 12];
    const float* bt = (const float*)d_in[base + 13];
    float* out = (float*)d_out;

    float *tmp, *o1;
    __half *qh, *kh, *vh, *ctxh, *o1h, *hidh, *xh, *wt;
    cudaGetSymbolAddress((void**)&qh,   g_qh);
    cudaGetSymbolAddress((void**)&kh,   g_kh);
    cudaGetSymbolAddress((void**)&vh,   g_vh);
    cudaGetSymbolAddress((void**)&ctxh, g_ctxh);
    cudaGetSymbolAddress((void**)&tmp,  g_tmp);
    cudaGetSymbolAddress((void**)&o1,   g_o1);
    cudaGetSymbolAddress((void**)&o1h,  g_o1h);
    cudaGetSymbolAddress((void**)&hidh, g_hidh);
    cudaGetSymbolAddress((void**)&xh,   g_xh);
    cudaGetSymbolAddress((void**)&wt,   g_wt);

    cudaFuncSetAttribute(gemm_h<0>, cudaFuncAttributeMaxDynamicSharedMemorySize, GEMM_SMEM);
    cudaFuncSetAttribute(gemm_h<1>, cudaFuncAttributeMaxDynamicSharedMemorySize, GEMM_SMEM);
    cudaFuncSetAttribute(gemm_h<2>, cudaFuncAttributeMaxDynamicSharedMemorySize, GEMM_SMEM);
    cudaFuncSetAttribute(attn_kernel, cudaFuncAttributeMaxDynamicSharedMemorySize, ATTN_SMEM);

    // ---- preprocessing: fp16 conversions ----
    {
        int n4 = MM * DD / 4;
        hconv_kernel<<<(n4 + 255) / 256, 256>>>(x, xh, n4);
        wtrans_kernel<<<dim3(DD/32, DD/32), 256>>>(Wq, wt + OFF_WQ, DD, DD);
        wtrans_kernel<<<dim3(DD/32, DD/32), 256>>>(Wk, wt + OFF_WK, DD, DD);
        wtrans_kernel<<<dim3(DD/32, DD/32), 256>>>(Wv, wt + OFF_WV, DD, DD);
        wtrans_kernel<<<dim3(DD/32, DD/32), 256>>>(Wo, wt + OFF_WO, DD, DD);
        wtrans_kernel<<<dim3(FF/32, DD/32), 256>>>(W1, wt + OFF_W1, DD, FF);
        wtrans_kernel<<<dim3(DD/32, FF/32), 256>>>(W2, wt + OFF_W2, FF, DD);
    }

    dim3 gD(DD / 128, MM / 128);   // (8, 128)
    dim3 gF(FF / 128, MM / 128);   // (32, 128)

    // QKV projections (Q pre-scaled by 1/sqrt(64) = 0.125)
    gemm_h<2><<<gD, 256, GEMM_SMEM>>>(xh, wt + OFF_WQ, bq, 0, qh, MM, DD, DD, 0.125f);
    gemm_h<2><<<gD, 256, GEMM_SMEM>>>(xh, wt + OFF_WK, bk, 0, kh, MM, DD, DD, 1.0f);
    gemm_h<2><<<gD, 256, GEMM_SMEM>>>(xh, wt + OFF_WV, bv, 0, vh, MM, DD, DD, 1.0f);

    attn_kernel<<<dim3(SS / 64, HH, BB), 256, ATTN_SMEM>>>(adj, mask);

    gemm_h<0><<<gD, 256, GEMM_SMEM>>>(ctxh, wt + OFF_WO, bo, tmp, 0, MM, DD, DD, 1.0f);
    ln_kernel<<<MM, 256>>>(x, tmp, gm, bt, o1, o1h);

    gemm_h<1><<<gF, 256, GEMM_SMEM>>>(o1h, wt + OFF_W1, b1, 0, hidh, MM, FF, DD, 1.0f);
    gemm_h<0><<<gD, 256, GEMM_SMEM>>>(hidh, wt + OFF_W2, b2, tmp, 0, MM, DD, FF, 1.0f);
    ln_kernel<<<MM, 256>>>(o1, tmp, gm, bt, out, 0);
}

// round 15
// speedup vs baseline: 2.0911x; 1.1317x over previous
#include <cuda_runtime.h>
#include <cuda_fp16.h>
#include <cstdint>
#include <math.h>

// Problem dims (fixed by the reference)
#define BB 32
#define SS 512
#define DD 1024
#define HH 16
#define DK 64
#define FF 4096
#define MM (BB*SS)   // 16384 rows

// ---------------------------------------------------------------------------
// Scratch (static device arrays; no allocation APIs anywhere)
// ---------------------------------------------------------------------------
__device__ __half g_qh [BB*HH*SS*DK];   // [B,H,S,dk] fp16, Q pre-scaled by 1/8
__device__ __half g_kh [BB*HH*SS*DK];
__device__ __half g_vh [BB*HH*SS*DK];
__device__ __half g_ctxh[MM*DD];        // [B,S,D] fp16
__device__ float  g_tmp[MM*DD];         // attn_out / ffn_out (fp32)
__device__ float  g_o1 [MM*DD];         // out1 fp32 (residual)
__device__ __half g_o1h[MM*DD];         // out1 fp16 (GEMM input)
__device__ __half g_hidh[(size_t)MM*FF];// FFN hidden fp16
__device__ __half g_xh [MM*DD];         // x fp16
__device__ __half g_wt [12582912];      // all 6 weights fp16, TRANSPOSED [N,K]

#define OFF_WQ 0
#define OFF_WK (OFF_WQ + DD*DD)
#define OFF_WV (OFF_WK + DD*DD)
#define OFF_WO (OFF_WV + DD*DD)
#define OFF_W1 (OFF_WO + DD*DD)
#define OFF_W2 (OFF_W1 + DD*FF)

// ---------------------------------------------------------------------------
// Helpers
// ---------------------------------------------------------------------------
__device__ __forceinline__ void mma16(float* c, uint32_t a0, uint32_t a1,
                                      uint32_t a2, uint32_t a3,
                                      uint32_t b0, uint32_t b1) {
    asm volatile(
        "mma.sync.aligned.m16n8k16.row.col.f32.f16.f16.f32 "
        "{%0,%1,%2,%3}, {%4,%5,%6,%7}, {%8,%9}, {%0,%1,%2,%3};\n"
        : "+f"(c[0]), "+f"(c[1]), "+f"(c[2]), "+f"(c[3])
        : "r"(a0), "r"(a1), "r"(a2), "r"(a3), "r"(b0), "r"(b1));
}

__device__ __forceinline__ void cpa16(uint32_t dst, const void* src) {
    asm volatile("cp.async.cg.shared.global [%0], [%1], 16;\n" :: "r"(dst), "l"(src));
}
#define CP_COMMIT() asm volatile("cp.async.commit_group;\n" ::: "memory")
#define CP_WAIT(n)  asm volatile("cp.async.wait_group %0;\n" :: "n"(n) : "memory")

__device__ __forceinline__ void ldmx4t(uint32_t& r0, uint32_t& r1,
                                       uint32_t& r2, uint32_t& r3, uint32_t addr) {
    asm volatile(
        "ldmatrix.sync.aligned.m8n8.x4.trans.shared.b16 {%0,%1,%2,%3}, [%4];"
        : "=r"(r0), "=r"(r1), "=r"(r2), "=r"(r3) : "r"(addr));
}

__device__ __forceinline__ float gelu_erf(float x) {
    return 0.5f * x * (1.0f + erff(x * 0.70710678118654752440f));
}

__device__ __forceinline__ uint32_t ldh32(const __half* p) {
    return *(const uint32_t*)p;
}

// ---------------------------------------------------------------------------
// Preprocessing: fp32 -> fp16 convert; transpose+convert weights to [N,K]
// ---------------------------------------------------------------------------
__global__ void __launch_bounds__(256)
hconv_kernel(const float* __restrict__ src, __half* __restrict__ dst, int n4)
{
    int i = blockIdx.x * 256 + threadIdx.x;
    if (i < n4) {
        float4 v = ((const float4*)src)[i];
        ((__half2*)dst)[i*2]   = __floats2half2_rn(v.x, v.y);
        ((__half2*)dst)[i*2+1] = __floats2half2_rn(v.z, v.w);
    }
}

__global__ void __launch_bounds__(256)
wtrans_kernel(const float* __restrict__ W, __half* __restrict__ Wt, int K, int N)
{
    __shared__ float t[32][33];
    int n0 = blockIdx.x * 32, k0 = blockIdx.y * 32;
    int tx = threadIdx.x & 31, ty = threadIdx.x >> 5;  // 32x8
#pragma unroll
    for (int j = 0; j < 4; j++)
        t[ty + j*8][tx] = W[(size_t)(k0 + ty + j*8) * N + n0 + tx];
    __syncthreads();
#pragma unroll
    for (int j = 0; j < 4; j++)
        Wt[(size_t)(n0 + ty + j*8) * K + k0 + tx] = __float2half(t[tx][ty + j*8]);
}

// ---------------------------------------------------------------------------
// FP16 GEMM: C[M,N] = A[M,K] @ Wt[N,K]^T + bias
//   EPI 0: fp32 store
//   EPI 1: GELU -> fp16 store (hidden)
//   EPI 2: fused QKV: per-CTA select {bias,dst,alpha} by n0>>10; fp16 scatter
//          into [B,H,S,dk]
// BM=128, BN=128, BK=32; 256 threads = 8 warps (2x4), warp tile 64x32.
// 4-stage cp.async; smem stride 40 halves.
// ---------------------------------------------------------------------------
#define HST 40
#define STG_H (256*HST)
#define GEMM_SMEM (4*STG_H*2)

template <int EPI>
__global__ void __launch_bounds__(256)
gemm_h(const __half* __restrict__ A, const __half* __restrict__ Bt,
       const float* __restrict__ bias0, const float* __restrict__ bias1,
       const float* __restrict__ bias2,
       float* __restrict__ Cf,
       __half* __restrict__ Ch0, __half* __restrict__ Ch1, __half* __restrict__ Ch2,
       int M, int N, int K)
{
    extern __shared__ __half hsm[];
    const uint32_t sb = (uint32_t)__cvta_generic_to_shared(hsm);

    const int tid  = threadIdx.x;
    const int m0   = blockIdx.y * 128;
    const int n0   = blockIdx.x * 128;
    const int warp = tid >> 5, lane = tid & 31;
    const int g    = lane >> 2, tg = lane & 3;
    const int warpM = warp & 1;
    const int warpN = warp >> 1;

    const int rlow = tid & 7, qc = (tid >> 3) & 3, w8 = tid >> 5;

    float acc[4][4][4];
#pragma unroll
    for (int a = 0; a < 4; a++)
#pragma unroll
        for (int b = 0; b < 4; b++)
#pragma unroll
            for (int c = 0; c < 4; c++) acc[a][b][c] = 0.f;

    const int nT = K / 32;

    auto issue = [&](int st, int c) {
        const int k0 = c * 32;
        const uint32_t base = sb + st * (STG_H * 2);
#pragma unroll
        for (int it = 0; it < 2; it++) {
            int r = rlow + 8 * w8 + 64 * it;
            cpa16(base + (uint32_t)(r * 80 + qc * 16),
                  A + (size_t)(m0 + r) * K + k0 + qc * 8);
            cpa16(base + (uint32_t)(128 * 80 + r * 80 + qc * 16),
                  Bt + (size_t)(n0 + r) * K + k0 + qc * 8);
        }
        CP_COMMIT();
    };

    issue(0, 0);
    issue(1, 1);
    issue(2, 2);

    for (int t = 0; t < nT; t++) {
        if (t + 3 < nT) CP_WAIT(2);
        else            CP_WAIT(0);
        __syncthreads();
        if (t + 3 < nT) issue((t + 3) & 3, t + 3);

        const __half* pA = hsm + (t & 3) * STG_H;
        const __half* pB = pA + 128 * HST;
#pragma unroll
        for (int ks = 0; ks < 2; ks++) {
            uint32_t af[4][4];
#pragma unroll
            for (int mf = 0; mf < 4; mf++) {
                int r = warpM * 64 + mf * 16 + g;
                int c = ks * 16 + 2 * tg;
                af[mf][0] = ldh32(pA + r * HST + c);
                af[mf][1] = ldh32(pA + (r + 8) * HST + c);
                af[mf][2] = ldh32(pA + r * HST + c + 8);
                af[mf][3] = ldh32(pA + (r + 8) * HST + c + 8);
            }
#pragma unroll
            for (int nf = 0; nf < 4; nf++) {
                int n = warpN * 32 + nf * 8 + g;
                int c = ks * 16 + 2 * tg;
                uint32_t b0 = ldh32(pB + n * HST + c);
                uint32_t b1 = ldh32(pB + n * HST + c + 8);
#pragma unroll
                for (int mf = 0; mf < 4; mf++)
                    mma16(acc[mf][nf], af[mf][0], af[mf][1], af[mf][2], af[mf][3], b0, b1);
            }
        }
    }

    // ---- epilogue ----
    const float* bias = bias0;
    __half* dstQKV = Ch0;
    float alpha = 1.0f;
    if (EPI == 2) {
        int which = n0 >> 10;
        bias   = (which == 0) ? bias0 : (which == 1 ? bias1 : bias2);
        dstQKV = (which == 0) ? Ch0   : (which == 1 ? Ch1   : Ch2);
        alpha  = (which == 0) ? 0.125f : 1.0f;
    }
#pragma unroll
    for (int mf = 0; mf < 4; mf++) {
#pragma unroll
        for (int nf = 0; nf < 4; nf++) {
            int row = m0 + warpM * 64 + mf * 16 + g;
            int col = n0 + warpN * 32 + nf * 8 + 2 * tg;
            int lcol = (EPI == 2) ? (col & 1023) : col;
            float b0 = bias[lcol], b1 = bias[lcol + 1];
            float v0 = acc[mf][nf][0] + b0;
            float v1 = acc[mf][nf][1] + b1;
            float v2 = acc[mf][nf][2] + b0;
            float v3 = acc[mf][nf][3] + b1;
            if (EPI == 0) {
                *(float2*)(Cf + (size_t)row * N + col)       = make_float2(v0, v1);
                *(float2*)(Cf + (size_t)(row + 8) * N + col) = make_float2(v2, v3);
            } else if (EPI == 1) {
                *(__half2*)(Ch0 + (size_t)row * N + col)       = __floats2half2_rn(gelu_erf(v0), gelu_erf(v1));
                *(__half2*)(Ch0 + (size_t)(row + 8) * N + col) = __floats2half2_rn(gelu_erf(v2), gelu_erf(v3));
            } else { // EPI == 2: fused QKV scatter into [B,H,S,dk]
                int bI = row >> 9, s = row & 511;
                int h  = lcol >> 6, d = lcol & 63;
                size_t base = (((size_t)(bI * HH + h)) * SS + s) * DK + d;
                *(__half2*)(dstQKV + base)          = __floats2half2_rn(v0 * alpha, v1 * alpha);
                *(__half2*)(dstQKV + base + 8 * DK) = __floats2half2_rn(v2 * alpha, v3 * alpha);
            }
        }
    }
}

// ---------------------------------------------------------------------------
// Attention: one CTA per (b, h, 64 q-rows).
//  - adj preloaded into score smem via cp.async (own group)
//  - K and V chunks triple-buffered cp.async, issue-ahead pipeline
//  - softmax writes P fp16 IN-PLACE into the score buffer (stride 1032 halves)
//  - V0/V1 prefetched before softmax
// ---------------------------------------------------------------------------
#define SSF_STRIDE 516           // fp32 words per score row (2064 B)
#define SPW 1032                 // halves per P row (same physical rows)
#define SQH_STRIDE 72            // halves per K/V row (144 B)
#define KVBUF 9216               // bytes per KV buffer (64*144)
#define AT_Q_OFF  (64*SSF_STRIDE*4)              // 132096
#define AT_KV_OFF (AT_Q_OFF + 64*SQH_STRIDE*2)   // 141312
#define ATTN_SMEM (AT_KV_OFF + 3*KVBUF)          // 168960

__global__ void __launch_bounds__(256)
attn_kernel(const float* __restrict__ adj, const int* __restrict__ mask)
{
    extern __shared__ char smb[];
    float*  sS  = (float*)smb;
    __half* sPh = (__half*)smb;                 // P aliases scores (per-row in-place)
    __half* sQh = (__half*)(smb + AT_Q_OFF);
    const uint32_t sbu = (uint32_t)__cvta_generic_to_shared(smb);
    __shared__ float sMaskB[SS];

    const int qt = blockIdx.x, h = blockIdx.y, b = blockIdx.z;
    const int q0 = qt * 64;
    const int tid = threadIdx.x;
    const int warp = tid >> 5, lane = tid & 31;
    const int g = lane >> 2, tg = lane & 3;

    const size_t headBase = ((size_t)(b * HH + h)) * SS * DK;

    // ---- group 0: adj -> score smem (64 rows x 2048B, row stride 2064B) ----
    {
        const float* asrc = adj + ((size_t)b * SS + q0) * SS;
#pragma unroll
        for (int i = 0; i < 32; i++) {
            int u = tid + i * 256;
            int r = u >> 7, cc = u & 127;
            cpa16(sbu + (uint32_t)(r * 2064 + cc * 16), asrc + (size_t)r * SS + cc * 4);
        }
        CP_COMMIT();
    }

    // KV chunk loaders (64 rows x 128B into buffer bf)
    auto issueK = [&](int ch, int bf) {
#pragma unroll
        for (int i = 0; i < 2; i++) {
            int u = tid + i * 256;
            int r = u >> 3, c8 = u & 7;
            cpa16(sbu + AT_KV_OFF + bf * KVBUF + (uint32_t)(r * 144 + c8 * 16),
                  g_kh + headBase + (size_t)(ch * 64 + r) * DK + c8 * 8);
        }
        CP_COMMIT();
    };
    auto issueV = [&](int ch, int bf) {
#pragma unroll
        for (int i = 0; i < 2; i++) {
            int u = tid + i * 256;
            int r = u >> 3, c8 = u & 7;
            cpa16(sbu + AT_KV_OFF + bf * KVBUF + (uint32_t)(r * 144 + c8 * 16),
                  g_vh + headBase + (size_t)(ch * 64 + r) * DK + c8 * 8);
        }
        CP_COMMIT();
    };

    issueK(0, 0);
    issueK(1, 1);

    // mask bias + Q tile (plain loads; covered by the syncthreads in iter 0)
    for (int i = tid; i < SS; i += 256)
        sMaskB[i] = -1e9f * (float)mask[b * SS + i];
#pragma unroll
    for (int i = 0; i < 2; i++) {
        int s = tid + i * 256;
        int r = s >> 3, c8 = s & 7;
        *(uint4*)(sQh + r * SQH_STRIDE + c8 * 8) =
            *(const uint4*)(g_qh + headBase + (size_t)(q0 + r) * DK + c8 * 8);
    }

    // ---- phase 1: scores = Q K^T + maskbias + adj(preloaded) ----
    {
        const int warpQ = warp & 1;   // 32 q-rows
        const int warpK = warp >> 1;  // 16 keys
        for (int ch = 0; ch < 8; ch++) {
            if (ch + 2 < 8) CP_WAIT(1);
            else            CP_WAIT(0);
            __syncthreads();
            if (ch + 2 < 8) issueK(ch + 2, (ch + 2) % 3);

            const __half* sK = (__half*)(smb + AT_KV_OFF + (ch % 3) * KVBUF);

            float acc[2][2][4];
#pragma unroll
            for (int a = 0; a < 2; a++)
#pragma unroll
                for (int n = 0; n < 2; n++)
#pragma unroll
                    for (int c = 0; c < 4; c++) acc[a][n][c] = 0.f;

#pragma unroll
            for (int ks = 0; ks < 4; ks++) {
                uint32_t af[2][4];
#pragma unroll
                for (int mf = 0; mf < 2; mf++) {
                    int r = warpQ * 32 + mf * 16 + g;
                    int c = ks * 16 + 2 * tg;
                    af[mf][0] = ldh32(sQh + r * SQH_STRIDE + c);
                    af[mf][1] = ldh32(sQh + (r + 8) * SQH_STRIDE + c);
                    af[mf][2] = ldh32(sQh + r * SQH_STRIDE + c + 8);
                    af[mf][3] = ldh32(sQh + (r + 8) * SQH_STRIDE + c + 8);
                }
#pragma unroll
                for (int nf = 0; nf < 2; nf++) {
                    int n = warpK * 16 + nf * 8 + g;
                    int c = ks * 16 + 2 * tg;
                    uint32_t b0 = ldh32(sK + n * SQH_STRIDE + c);
                    uint32_t b1 = ldh32(sK + n * SQH_STRIDE + c + 8);
                    mma16(acc[0][nf], af[0][0], af[0][1], af[0][2], af[0][3], b0, b1);
                    mma16(acc[1][nf], af[1][0], af[1][1], af[1][2], af[1][3], b0, b1);
                }
            }
#pragma unroll
            for (int mf = 0; mf < 2; mf++) {
#pragma unroll
                for (int nf = 0; nf < 2; nf++) {
                    int row = warpQ * 32 + mf * 16 + g;
                    int col = ch * 64 + warpK * 16 + nf * 8 + 2 * tg;
                    float* p0 = sS + row * SSF_STRIDE + col;
                    float* p1 = sS + (row + 8) * SSF_STRIDE + col;
                    p0[0] = acc[mf][nf][0] + sMaskB[col]     + p0[0];
                    p0[1] = acc[mf][nf][1] + sMaskB[col + 1] + p0[1];
                    p1[0] = acc[mf][nf][2] + sMaskB[col]     + p1[0];
                    p1[1] = acc[mf][nf][3] + sMaskB[col + 1] + p1[1];
                }
            }
        }
    }

    // prefetch V0/V1 while softmax runs (buffers 0 and 2 are free for all warps)
    issueV(0, 0);
    issueV(1, 2);
    __syncthreads();

    // ---- phase 2: softmax (fp32), P written fp16 in-place ----
    {
        for (int r8 = 0; r8 < 8; r8++) {
            const int row = warp * 8 + r8;
            const float* Sr = sS + row * SSF_STRIDE;
            float2 v[8];
            float mx = -3.4e38f;
#pragma unroll
            for (int i = 0; i < 8; i++) {
                v[i] = *(const float2*)(Sr + 2 * lane + 64 * i);
                mx = fmaxf(mx, fmaxf(v[i].x, v[i].y));
            }
#pragma unroll
            for (int o = 16; o; o >>= 1) mx = fmaxf(mx, __shfl_xor_sync(0xffffffffu, mx, o));
            float sum = 0.f;
#pragma unroll
            for (int i = 0; i < 8; i++) {
                v[i].x = __expf(v[i].x - mx);
                v[i].y = __expf(v[i].y - mx);
                sum += v[i].x + v[i].y;
            }
#pragma unroll
            for (int o = 16; o; o >>= 1) sum += __shfl_xor_sync(0xffffffffu, sum, o);
            float inv = 1.f / sum;
            __half* Pr = sPh + row * SPW;
#pragma unroll
            for (int i = 0; i < 8; i++)
                *(__half2*)(Pr + 2 * lane + 64 * i) = __floats2half2_rn(v[i].x * inv, v[i].y * inv);
        }
        __syncthreads();
    }

    // ---- phase 3: ctx = P @ V ----
    {
        const int warpQ = warp & 1;
        const int warpD = warp >> 1;   // 16 dims
        const int vb[3] = {0, 2, 1};   // V_ch -> buffer vb[ch%3]
        float o[2][2][4];
#pragma unroll
        for (int a = 0; a < 2; a++)
#pragma unroll
            for (int n = 0; n < 2; n++)
#pragma unroll
                for (int c = 0; c < 4; c++) o[a][n][c] = 0.f;

        for (int ch = 0; ch < 8; ch++) {
            if (ch + 2 < 8) CP_WAIT(1);
            else            CP_WAIT(0);
            __syncthreads();
            if (ch + 2 < 8) issueV(ch + 2, vb[(ch + 2) % 3]);

            const uint32_t vbase = sbu + AT_KV_OFF + vb[ch % 3] * KVBUF;

#pragma unroll
            for (int ks = 0; ks < 4; ks++) {
                uint32_t af[2][4];
#pragma unroll
                for (int mf = 0; mf < 2; mf++) {
                    int r = warpQ * 32 + mf * 16 + g;
                    int c = ch * 64 + ks * 16 + 2 * tg;
                    af[mf][0] = ldh32(sPh + r * SPW + c);
                    af[mf][1] = ldh32(sPh + (r + 8) * SPW + c);
                    af[mf][2] = ldh32(sPh + r * SPW + c + 8);
                    af[mf][3] = ldh32(sPh + (r + 8) * SPW + c + 8);
                }
                uint32_t bv[4];
                {
                    int key = ks * 16 + (lane & 7) + (lane & 8);
                    int dmc = warpD * 16 + ((lane >> 4) << 3);
                    ldmx4t(bv[0], bv[1], bv[2], bv[3],
                           vbase + (uint32_t)(key * 144 + dmc * 2));
                }
#pragma unroll
                for (int nb = 0; nb < 2; nb++) {
                    mma16(o[0][nb], af[0][0], af[0][1], af[0][2], af[0][3], bv[nb*2], bv[nb*2+1]);
                    mma16(o[1][nb], af[1][0], af[1][1], af[1][2], af[1][3], bv[nb*2], bv[nb*2+1]);
                }
            }
        }

        // ctx fp16 in [B,S,D] (D index = h*64 + d)
#pragma unroll
        for (int mf = 0; mf < 2; mf++) {
#pragma unroll
            for (int nb = 0; nb < 2; nb++) {
                int q = q0 + warpQ * 32 + mf * 16 + g;
                int d = warpD * 16 + nb * 8 + 2 * tg;
                size_t base = ((size_t)b * SS + q) * DD + h * DK + d;
                *(__half2*)(g_ctxh + base)          = __floats2half2_rn(o[mf][nb][0], o[mf][nb][1]);
                *(__half2*)(g_ctxh + base + 8 * DD) = __floats2half2_rn(o[mf][nb][2], o[mf][nb][3]);
            }
        }
    }
}

// ---------------------------------------------------------------------------
// Residual + LayerNorm (torch semantics: unbiased std, / (std + eps)).
// ---------------------------------------------------------------------------
__global__ void __launch_bounds__(256)
ln_kernel(const float* __restrict__ a, const float* __restrict__ r,
          const float* __restrict__ gamma, const float* __restrict__ beta,
          float* __restrict__ out, __half* __restrict__ oh)
{
    __shared__ float red[8];
    const int row = blockIdx.x;
    const int tid = threadIdx.x;
    const int warp = tid >> 5, lane = tid & 31;

    float4 va = ((const float4*)(a + (size_t)row * DD))[tid];
    float4 vr = ((const float4*)(r + (size_t)row * DD))[tid];
    float v0 = va.x + vr.x, v1 = va.y + vr.y, v2 = va.z + vr.z, v3 = va.w + vr.w;

    float s = v0 + v1 + v2 + v3;
#pragma unroll
    for (int o = 16; o; o >>= 1) s += __shfl_xor_sync(0xffffffffu, s, o);
    if (lane == 0) red[warp] = s;
    __syncthreads();
    float tot = 0.f;
#pragma unroll
    for (int i = 0; i < 8; i++) tot += red[i];
    float mean = tot * (1.0f / 1024.0f);
    __syncthreads();

    float d0 = v0 - mean, d1 = v1 - mean, d2 = v2 - mean, d3 = v3 - mean;
    float sq = d0 * d0 + d1 * d1 + d2 * d2 + d3 * d3;
#pragma unroll
    for (int o = 16; o; o >>= 1) sq += __shfl_xor_sync(0xffffffffu, sq, o);
    if (lane == 0) red[warp] = sq;
    __syncthreads();
    float tot2 = 0.f;
#pragma unroll
    for (int i = 0; i < 8; i++) tot2 += red[i];
    float var = tot2 * (1.0f / 1023.0f);         // ddof=1
    float inv = 1.0f / (sqrtf(var) + 1e-6f);      // (std + eps)

    float4 gm = ((const float4*)gamma)[tid];
    float4 bt = ((const float4*)beta)[tid];
    float4 o4;
    o4.x = gm.x * d0 * inv + bt.x;
    o4.y = gm.y * d1 * inv + bt.y;
    o4.z = gm.z * d2 * inv + bt.z;
    o4.w = gm.w * d3 * inv + bt.w;
    ((float4*)(out + (size_t)row * DD))[tid] = o4;
    if (oh) {
        size_t o = (size_t)row * DD + tid * 4;
        *(__half2*)(oh + o)     = __floats2half2_rn(o4.x, o4.y);
        *(__half2*)(oh + o + 2) = __floats2half2_rn(o4.z, o4.w);
    }
}

// ---------------------------------------------------------------------------
// Launch
// ---------------------------------------------------------------------------
extern "C" void kernel_launch(void* const* d_in, const int* in_sizes, int n_in,
                              void* d_out, int out_size)
{
    const float* x    = (const float*)d_in[0];
    const int*   mask = (const int*)  d_in[1];
    const float* adj  = (const float*)d_in[2];
    int base = (n_in > 3 && in_sizes[3] == 1) ? 4 : 3;
    const float* Wq = (const float*)d_in[base + 0];
    const float* bq = (const float*)d_in[base + 1];
    const float* Wk = (const float*)d_in[base + 2];
    const float* bk = (const float*)d_in[base + 3];
    const float* Wv = (const float*)d_in[base + 4];
    const float* bv = (const float*)d_in[base + 5];
    const float* Wo = (const float*)d_in[base + 6];
    const float* bo = (const float*)d_in[base + 7];
    const float* W1 = (const float*)d_in[base + 8];
    const float* b1 = (const float*)d_in[base + 9];
    const float* W2 = (const float*)d_in[base + 10];
    const float* b2 = (const float*)d_in[base + 11];
    const float* gm = (const float*)d_in[base + 12];
    const float* bt = (const float*)d_in[base + 13];
    float* out = (float*)d_out;

    float *tmp, *o1;
    __half *qh, *kh, *vh, *ctxh, *o1h, *hidh, *xh, *wt;
    cudaGetSymbolAddress((void**)&qh,   g_qh);
    cudaGetSymbolAddress((void**)&kh,   g_kh);
    cudaGetSymbolAddress((void**)&vh,   g_vh);
    cudaGetSymbolAddress((void**)&ctxh, g_ctxh);
    cudaGetSymbolAddress((void**)&tmp,  g_tmp);
    cudaGetSymbolAddress((void**)&o1,   g_o1);
    cudaGetSymbolAddress((void**)&o1h,  g_o1h);
    cudaGetSymbolAddress((void**)&hidh, g_hidh);
    cudaGetSymbolAddress((void**)&xh,   g_xh);
    cudaGetSymbolAddress((void**)&wt,   g_wt);

    cudaFuncSetAttribute(gemm_h<0>, cudaFuncAttributeMaxDynamicSharedMemorySize, GEMM_SMEM);
    cudaFuncSetAttribute(gemm_h<1>, cudaFuncAttributeMaxDynamicSharedMemorySize, GEMM_SMEM);
    cudaFuncSetAttribute(gemm_h<2>, cudaFuncAttributeMaxDynamicSharedMemorySize, GEMM_SMEM);
    cudaFuncSetAttribute(attn_kernel, cudaFuncAttributeMaxDynamicSharedMemorySize, ATTN_SMEM);

    // ---- preprocessing: fp16 conversions ----
    {
        int n4 = MM * DD / 4;
        hconv_kernel<<<(n4 + 255) / 256, 256>>>(x, xh, n4);
        wtrans_kernel<<<dim3(DD/32, DD/32), 256>>>(Wq, wt + OFF_WQ, DD, DD);
        wtrans_kernel<<<dim3(DD/32, DD/32), 256>>>(Wk, wt + OFF_WK, DD, DD);
        wtrans_kernel<<<dim3(DD/32, DD/32), 256>>>(Wv, wt + OFF_WV, DD, DD);
        wtrans_kernel<<<dim3(DD/32, DD/32), 256>>>(Wo, wt + OFF_WO, DD, DD);
        wtrans_kernel<<<dim3(FF/32, DD/32), 256>>>(W1, wt + OFF_W1, DD, FF);
        wtrans_kernel<<<dim3(DD/32, FF/32), 256>>>(W2, wt + OFF_W2, FF, DD);
    }

    dim3 gQKV(3 * DD / 128, MM / 128);  // (24, 128)
    dim3 gD(DD / 128, MM / 128);        // (8, 128)
    dim3 gF(FF / 128, MM / 128);        // (32, 128)

    // fused QKV projection (rows 0..3071 of wt are Wq^T|Wk^T|Wv^T)
    gemm_h<2><<<gQKV, 256, GEMM_SMEM>>>(xh, wt, bq, bk, bv, 0, qh, kh, vh, MM, 3 * DD, DD);

    attn_kernel<<<dim3(SS / 64, HH, BB), 256, ATTN_SMEM>>>(adj, mask);

    gemm_h<0><<<gD, 256, GEMM_SMEM>>>(ctxh, wt + OFF_WO, bo, 0, 0, tmp, 0, 0, 0, MM, DD, DD);
    ln_kernel<<<MM, 256>>>(x, tmp, gm, bt, o1, o1h);

    gemm_h<1><<<gF, 256, GEMM_SMEM>>>(o1h, wt + OFF_W1, b1, 0, 0, 0, hidh, 0, 0, MM, FF, DD);
    gemm_h<0><<<gD, 256, GEMM_SMEM>>>(hidh, wt + OFF_W2, b2, 0, 0, tmp, 0, 0, 0, MM, DD, FF);
    ln_kernel<<<MM, 256>>>(o1, tmp, gm, bt, out, 0);
}

// round 16
// speedup vs baseline: 2.2411x; 1.0718x over previous
#include <cuda_runtime.h>
#include <cuda_fp16.h>
#include <cstdint>
#include <math.h>

// Problem dims (fixed by the reference)
#define BB 32
#define SS 512
#define DD 1024
#define HH 16
#define DK 64
#define FF 4096
#define MM (BB*SS)   // 16384 rows

// ---------------------------------------------------------------------------
// Scratch (static device arrays; no allocation APIs anywhere)
// ---------------------------------------------------------------------------
__device__ __half g_qh [BB*HH*SS*DK];   // [B,H,S,dk] fp16, Q pre-scaled by 1/8
__device__ __half g_kh [BB*HH*SS*DK];
__device__ __half g_vh [BB*HH*SS*DK];
__device__ __half g_ctxh[MM*DD];        // [B,S,D] fp16
__device__ float  g_tmp[MM*DD];         // attn_out / ffn_out (fp32)
__device__ float  g_o1 [MM*DD];         // out1 fp32 (residual)
__device__ __half g_o1h[MM*DD];         // out1 fp16 (GEMM input)
__device__ __half g_hidh[(size_t)MM*FF];// FFN hidden fp16
__device__ __half g_xh [MM*DD];         // x fp16
__device__ __half g_wt [12582912];      // all 6 weights fp16, TRANSPOSED [N,K]

#define OFF_WQ 0
#define OFF_WK (OFF_WQ + DD*DD)
#define OFF_WV (OFF_WK + DD*DD)
#define OFF_WO (OFF_WV + DD*DD)
#define OFF_W1 (OFF_WO + DD*DD)
#define OFF_W2 (OFF_W1 + DD*FF)

// ---------------------------------------------------------------------------
// Helpers
// ---------------------------------------------------------------------------
__device__ __forceinline__ void mma16(float* c, uint32_t a0, uint32_t a1,
                                      uint32_t a2, uint32_t a3,
                                      uint32_t b0, uint32_t b1) {
    asm volatile(
        "mma.sync.aligned.m16n8k16.row.col.f32.f16.f16.f32 "
        "{%0,%1,%2,%3}, {%4,%5,%6,%7}, {%8,%9}, {%0,%1,%2,%3};\n"
        : "+f"(c[0]), "+f"(c[1]), "+f"(c[2]), "+f"(c[3])
        : "r"(a0), "r"(a1), "r"(a2), "r"(a3), "r"(b0), "r"(b1));
}

__device__ __forceinline__ void cpa16(uint32_t dst, const void* src) {
    asm volatile("cp.async.cg.shared.global [%0], [%1], 16;\n" :: "r"(dst), "l"(src));
}
#define CP_COMMIT() asm volatile("cp.async.commit_group;\n" ::: "memory")
#define CP_WAIT(n)  asm volatile("cp.async.wait_group %0;\n" :: "n"(n) : "memory")

__device__ __forceinline__ void ldmx4t(uint32_t& r0, uint32_t& r1,
                                       uint32_t& r2, uint32_t& r3, uint32_t addr) {
    asm volatile(
        "ldmatrix.sync.aligned.m8n8.x4.trans.shared.b16 {%0,%1,%2,%3}, [%4];"
        : "=r"(r0), "=r"(r1), "=r"(r2), "=r"(r3) : "r"(addr));
}

__device__ __forceinline__ float gelu_erf(float x) {
    return 0.5f * x * (1.0f + erff(x * 0.70710678118654752440f));
}

__device__ __forceinline__ uint32_t ldh32(const __half* p) {
    return *(const uint32_t*)p;
}

// ---------------------------------------------------------------------------
// Preprocessing: fp32 -> fp16 convert; transpose+convert weights to [N,K]
// ---------------------------------------------------------------------------
__global__ void __launch_bounds__(256)
hconv_kernel(const float* __restrict__ src, __half* __restrict__ dst, int n4)
{
    int i = blockIdx.x * 256 + threadIdx.x;
    if (i < n4) {
        float4 v = ((const float4*)src)[i];
        ((__half2*)dst)[i*2]   = __floats2half2_rn(v.x, v.y);
        ((__half2*)dst)[i*2+1] = __floats2half2_rn(v.z, v.w);
    }
}

__global__ void __launch_bounds__(256)
wtrans_kernel(const float* __restrict__ W, __half* __restrict__ Wt, int K, int N)
{
    __shared__ float t[32][33];
    int n0 = blockIdx.x * 32, k0 = blockIdx.y * 32;
    int tx = threadIdx.x & 31, ty = threadIdx.x >> 5;  // 32x8
#pragma unroll
    for (int j = 0; j < 4; j++)
        t[ty + j*8][tx] = W[(size_t)(k0 + ty + j*8) * N + n0 + tx];
    __syncthreads();
#pragma unroll
    for (int j = 0; j < 4; j++)
        Wt[(size_t)(n0 + ty + j*8) * K + k0 + tx] = __float2half(t[tx][ty + j*8]);
}

// Batched version for the four D x D weights (z selects the matrix)
__global__ void __launch_bounds__(256)
wtrans4_kernel(const float* __restrict__ W0, const float* __restrict__ W1,
               const float* __restrict__ W2, const float* __restrict__ W3,
               __half* __restrict__ Wt)
{
    __shared__ float t[32][33];
    const float* W = (blockIdx.z == 0) ? W0 : (blockIdx.z == 1) ? W1
                   : (blockIdx.z == 2) ? W2 : W3;
    __half* dst = Wt + (size_t)blockIdx.z * DD * DD;
    int n0 = blockIdx.x * 32, k0 = blockIdx.y * 32;
    int tx = threadIdx.x & 31, ty = threadIdx.x >> 5;
#pragma unroll
    for (int j = 0; j < 4; j++)
        t[ty + j*8][tx] = W[(size_t)(k0 + ty + j*8) * DD + n0 + tx];
    __syncthreads();
#pragma unroll
    for (int j = 0; j < 4; j++)
        dst[(size_t)(n0 + ty + j*8) * DD + k0 + tx] = __float2half(t[tx][ty + j*8]);
}

// ---------------------------------------------------------------------------
// FP16 GEMM: C[M,N] = A[M,K] @ Wt[N,K]^T + bias
//   EPI 0: fp32 store
//   EPI 1: GELU -> fp16 store (hidden)
//   EPI 2: fused QKV: per-CTA select {bias,dst,alpha} by n0>>10
// BM=128, BN=128, BK=32; 256 threads = 8 warps (2x4), warp tile 64x32.
// 4-stage cp.async; smem 80KB; __launch_bounds__(256,2) forces 2 CTAs/SM so
// barriers + epilogue of one CTA hide under the other's MMA stream.
// ---------------------------------------------------------------------------
#define HST 40
#define STG_H (256*HST)
#define GEMM_SMEM (4*STG_H*2)

template <int EPI>
__global__ void __launch_bounds__(256, 2)
gemm_h(const __half* __restrict__ A, const __half* __restrict__ Bt,
       const float* __restrict__ bias0, const float* __restrict__ bias1,
       const float* __restrict__ bias2,
       float* __restrict__ Cf,
       __half* __restrict__ Ch0, __half* __restrict__ Ch1, __half* __restrict__ Ch2,
       int M, int N, int K)
{
    extern __shared__ __half hsm[];
    const uint32_t sb = (uint32_t)__cvta_generic_to_shared(hsm);

    const int tid  = threadIdx.x;
    const int m0   = blockIdx.y * 128;
    const int n0   = blockIdx.x * 128;
    const int warp = tid >> 5, lane = tid & 31;
    const int g    = lane >> 2, tg = lane & 3;
    const int warpM = warp & 1;
    const int warpN = warp >> 1;

    const int rlow = tid & 7, qc = (tid >> 3) & 3, w8 = tid >> 5;

    float acc[4][4][4];
#pragma unroll
    for (int a = 0; a < 4; a++)
#pragma unroll
        for (int b = 0; b < 4; b++)
#pragma unroll
            for (int c = 0; c < 4; c++) acc[a][b][c] = 0.f;

    const int nT = K / 32;

    auto issue = [&](int st, int c) {
        const int k0 = c * 32;
        const uint32_t base = sb + st * (STG_H * 2);
#pragma unroll
        for (int it = 0; it < 2; it++) {
            int r = rlow + 8 * w8 + 64 * it;
            cpa16(base + (uint32_t)(r * 80 + qc * 16),
                  A + (size_t)(m0 + r) * K + k0 + qc * 8);
            cpa16(base + (uint32_t)(128 * 80 + r * 80 + qc * 16),
                  Bt + (size_t)(n0 + r) * K + k0 + qc * 8);
        }
        CP_COMMIT();
    };

    issue(0, 0);
    issue(1, 1);
    issue(2, 2);

    for (int t = 0; t < nT; t++) {
        if (t + 3 < nT) CP_WAIT(2);
        else            CP_WAIT(0);
        __syncthreads();
        if (t + 3 < nT) issue((t + 3) & 3, t + 3);

        const __half* pA = hsm + (t & 3) * STG_H;
        const __half* pB = pA + 128 * HST;
#pragma unroll
        for (int ks = 0; ks < 2; ks++) {
            uint32_t af[4][4];
#pragma unroll
            for (int mf = 0; mf < 4; mf++) {
                int r = warpM * 64 + mf * 16 + g;
                int c = ks * 16 + 2 * tg;
                af[mf][0] = ldh32(pA + r * HST + c);
                af[mf][1] = ldh32(pA + (r + 8) * HST + c);
                af[mf][2] = ldh32(pA + r * HST + c + 8);
                af[mf][3] = ldh32(pA + (r + 8) * HST + c + 8);
            }
#pragma unroll
            for (int nf = 0; nf < 4; nf++) {
                int n = warpN * 32 + nf * 8 + g;
                int c = ks * 16 + 2 * tg;
                uint32_t b0 = ldh32(pB + n * HST + c);
                uint32_t b1 = ldh32(pB + n * HST + c + 8);
#pragma unroll
                for (int mf = 0; mf < 4; mf++)
                    mma16(acc[mf][nf], af[mf][0], af[mf][1], af[mf][2], af[mf][3], b0, b1);
            }
        }
    }

    // ---- epilogue ----
    const float* bias = bias0;
    __half* dstQKV = Ch0;
    float alpha = 1.0f;
    if (EPI == 2) {
        int which = n0 >> 10;
        bias   = (which == 0) ? bias0 : (which == 1 ? bias1 : bias2);
        dstQKV = (which == 0) ? Ch0   : (which == 1 ? Ch1   : Ch2);
        alpha  = (which == 0) ? 0.125f : 1.0f;
    }
#pragma unroll
    for (int mf = 0; mf < 4; mf++) {
#pragma unroll
        for (int nf = 0; nf < 4; nf++) {
            int row = m0 + warpM * 64 + mf * 16 + g;
            int col = n0 + warpN * 32 + nf * 8 + 2 * tg;
            int lcol = (EPI == 2) ? (col & 1023) : col;
            float b0 = bias[lcol], b1 = bias[lcol + 1];
            float v0 = acc[mf][nf][0] + b0;
            float v1 = acc[mf][nf][1] + b1;
            float v2 = acc[mf][nf][2] + b0;
            float v3 = acc[mf][nf][3] + b1;
            if (EPI == 0) {
                *(float2*)(Cf + (size_t)row * N + col)       = make_float2(v0, v1);
                *(float2*)(Cf + (size_t)(row + 8) * N + col) = make_float2(v2, v3);
            } else if (EPI == 1) {
                *(__half2*)(Ch0 + (size_t)row * N + col)       = __floats2half2_rn(gelu_erf(v0), gelu_erf(v1));
                *(__half2*)(Ch0 + (size_t)(row + 8) * N + col) = __floats2half2_rn(gelu_erf(v2), gelu_erf(v3));
            } else {
                int bI = row >> 9, s = row & 511;
                int h  = lcol >> 6, d = lcol & 63;
                size_t base = (((size_t)(bI * HH + h)) * SS + s) * DK + d;
                *(__half2*)(dstQKV + base)          = __floats2half2_rn(v0 * alpha, v1 * alpha);
                *(__half2*)(dstQKV + base + 8 * DK) = __floats2half2_rn(v2 * alpha, v3 * alpha);
            }
        }
    }
}

// ---------------------------------------------------------------------------
// Attention: one CTA per (b, h, 32 q-rows). 96KB dynamic smem -> 2 CTAs/SM:
// one CTA's softmax (MUFU) overlaps the other's MMA (tensor).
//  - adj preloaded into score smem via cp.async (own group)
//  - K/V chunks (64 keys x 64 dims) triple-buffered cp.async issue-ahead
//  - softmax writes P fp16 IN-PLACE into the score buffer
//  - V0/V1 prefetched before softmax
// Phase 1 warp map: 8 warps x 8 keys (each warp all 32 q-rows).
// Phase 3 warp map: 2x4 (warpQ 16 rows, warpD 16 dims).
// ---------------------------------------------------------------------------
#define SSF_STRIDE 516                   // fp32 words per score row (2064 B)
#define SPW 1032                         // halves per P row (same rows)
#define KVBUF 9216                       // bytes per KV buffer (64*144)
#define AT_Q_OFF  (32*SSF_STRIDE*4)      // 66048
#define AT_KV_OFF (AT_Q_OFF + 32*72*2)   // 70656
#define ATTN_SMEM (AT_KV_OFF + 3*KVBUF)  // 98304

__global__ void __launch_bounds__(256, 2)
attn_kernel(const float* __restrict__ adj, const int* __restrict__ mask)
{
    extern __shared__ char smb[];
    float*  sS  = (float*)smb;
    __half* sPh = (__half*)smb;                 // P aliases scores (in-place)
    __half* sQh = (__half*)(smb + AT_Q_OFF);
    const uint32_t sbu = (uint32_t)__cvta_generic_to_shared(smb);
    __shared__ float sMaskB[SS];

    const int qt = blockIdx.x, h = blockIdx.y, b = blockIdx.z;
    const int q0 = qt * 32;
    const int tid = threadIdx.x;
    const int warp = tid >> 5, lane = tid & 31;
    const int g = lane >> 2, tg = lane & 3;

    const size_t headBase = ((size_t)(b * HH + h)) * SS * DK;

    // ---- group 0: adj -> score smem (32 rows x 2048B, row stride 2064B) ----
    {
        const float* asrc = adj + ((size_t)b * SS + q0) * SS;
#pragma unroll
        for (int i = 0; i < 16; i++) {
            int u = tid + i * 256;
            int r = u >> 7, cc = u & 127;
            cpa16(sbu + (uint32_t)(r * 2064 + cc * 16), asrc + (size_t)r * SS + cc * 4);
        }
        CP_COMMIT();
    }

    // KV chunk loaders (64 keys x 128B into buffer bf)
    auto issueK = [&](int ch, int bf) {
#pragma unroll
        for (int i = 0; i < 2; i++) {
            int u = tid + i * 256;
            int r = u >> 3, c8 = u & 7;
            cpa16(sbu + AT_KV_OFF + bf * KVBUF + (uint32_t)(r * 144 + c8 * 16),
                  g_kh + headBase + (size_t)(ch * 64 + r) * DK + c8 * 8);
        }
        CP_COMMIT();
    };
    auto issueV = [&](int ch, int bf) {
#pragma unroll
        for (int i = 0; i < 2; i++) {
            int u = tid + i * 256;
            int r = u >> 3, c8 = u & 7;
            cpa16(sbu + AT_KV_OFF + bf * KVBUF + (uint32_t)(r * 144 + c8 * 16),
                  g_vh + headBase + (size_t)(ch * 64 + r) * DK + c8 * 8);
        }
        CP_COMMIT();
    };

    issueK(0, 0);
    issueK(1, 1);

    // mask bias + Q tile (plain loads; covered by first-iteration syncthreads)
    for (int i = tid; i < SS; i += 256)
        sMaskB[i] = -1e9f * (float)mask[b * SS + i];
    {
        int r = tid >> 3, c8 = tid & 7;   // 32 rows x 64 halves in one pass
        *(uint4*)(sQh + r * 72 + c8 * 8) =
            *(const uint4*)(g_qh + headBase + (size_t)(q0 + r) * DK + c8 * 8);
    }

    // ---- phase 1: scores = Q K^T + maskbias + adj(preloaded) ----
    {
        for (int ch = 0; ch < 8; ch++) {
            if (ch + 2 < 8) CP_WAIT(1);
            else            CP_WAIT(0);
            __syncthreads();
            if (ch + 2 < 8) issueK(ch + 2, (ch + 2) % 3);

            const __half* sK = (__half*)(smb + AT_KV_OFF + (ch % 3) * KVBUF);

            float acc[2][4];
#pragma unroll
            for (int a = 0; a < 2; a++)
#pragma unroll
                for (int c = 0; c < 4; c++) acc[a][c] = 0.f;

#pragma unroll
            for (int ks = 0; ks < 4; ks++) {
                int c = ks * 16 + 2 * tg;
                uint32_t af[2][4];
#pragma unroll
                for (int mf = 0; mf < 2; mf++) {
                    int r = mf * 16 + g;
                    af[mf][0] = ldh32(sQh + r * 72 + c);
                    af[mf][1] = ldh32(sQh + (r + 8) * 72 + c);
                    af[mf][2] = ldh32(sQh + r * 72 + c + 8);
                    af[mf][3] = ldh32(sQh + (r + 8) * 72 + c + 8);
                }
                int n = warp * 8 + g;
                uint32_t b0 = ldh32(sK + n * 72 + c);
                uint32_t b1 = ldh32(sK + n * 72 + c + 8);
                mma16(acc[0], af[0][0], af[0][1], af[0][2], af[0][3], b0, b1);
                mma16(acc[1], af[1][0], af[1][1], af[1][2], af[1][3], b0, b1);
            }
#pragma unroll
            for (int mf = 0; mf < 2; mf++) {
                int row = mf * 16 + g;
                int col = ch * 64 + warp * 8 + 2 * tg;
                float* p0 = sS + row * SSF_STRIDE + col;
                float* p1 = sS + (row + 8) * SSF_STRIDE + col;
                p0[0] = acc[mf][0] + sMaskB[col]     + p0[0];
                p0[1] = acc[mf][1] + sMaskB[col + 1] + p0[1];
                p1[0] = acc[mf][2] + sMaskB[col]     + p1[0];
                p1[1] = acc[mf][3] + sMaskB[col + 1] + p1[1];
            }
        }
    }

    // prefetch V0/V1 while softmax runs
    issueV(0, 0);
    issueV(1, 2);
    __syncthreads();

    // ---- phase 2: softmax (fp32), P written fp16 in-place; 4 rows/warp ----
    {
        for (int r8 = 0; r8 < 4; r8++) {
            const int row = warp * 4 + r8;
            const float* Sr = sS + row * SSF_STRIDE;
            float2 v[8];
            float mx = -3.4e38f;
#pragma unroll
            for (int i = 0; i < 8; i++) {
                v[i] = *(const float2*)(Sr + 2 * lane + 64 * i);
                mx = fmaxf(mx, fmaxf(v[i].x, v[i].y));
            }
#pragma unroll
            for (int o = 16; o; o >>= 1) mx = fmaxf(mx, __shfl_xor_sync(0xffffffffu, mx, o));
            float sum = 0.f;
#pragma unroll
            for (int i = 0; i < 8; i++) {
                v[i].x = __expf(v[i].x - mx);
                v[i].y = __expf(v[i].y - mx);
                sum += v[i].x + v[i].y;
            }
#pragma unroll
            for (int o = 16; o; o >>= 1) sum += __shfl_xor_sync(0xffffffffu, sum, o);
            float inv = 1.f / sum;
            __half* Pr = sPh + row * SPW;
#pragma unroll
            for (int i = 0; i < 8; i++)
                *(__half2*)(Pr + 2 * lane + 64 * i) = __floats2half2_rn(v[i].x * inv, v[i].y * inv);
        }
        __syncthreads();
    }

    // ---- phase 3: ctx = P @ V (warpQ 16 rows x warpD 16 dims) ----
    {
        const int warpQ = warp & 1;
        const int warpD = warp >> 1;   // 0..3 -> 16 dims
        const int vb[3] = {0, 2, 1};   // V_ch -> buffer vb[ch%3]
        float o[2][4];
#pragma unroll
        for (int n = 0; n < 2; n++)
#pragma unroll
            for (int c = 0; c < 4; c++) o[n][c] = 0.f;

        for (int ch = 0; ch < 8; ch++) {
            if (ch + 2 < 8) CP_WAIT(1);
            else            CP_WAIT(0);
            __syncthreads();
            if (ch + 2 < 8) issueV(ch + 2, vb[(ch + 2) % 3]);

            const uint32_t vbase = sbu + AT_KV_OFF + vb[ch % 3] * KVBUF;

#pragma unroll
            for (int ks = 0; ks < 4; ks++) {
                int c = ch * 64 + ks * 16 + 2 * tg;
                int r = warpQ * 16 + g;
                uint32_t a0 = ldh32(sPh + r * SPW + c);
                uint32_t a1 = ldh32(sPh + (r + 8) * SPW + c);
                uint32_t a2 = ldh32(sPh + r * SPW + c + 8);
                uint32_t a3 = ldh32(sPh + (r + 8) * SPW + c + 8);
                uint32_t bv[4];
                {
                    int key = ks * 16 + (lane & 7) + (lane & 8);
                    int dmc = warpD * 16 + ((lane >> 4) << 3);
                    ldmx4t(bv[0], bv[1], bv[2], bv[3],
                           vbase + (uint32_t)(key * 144 + dmc * 2));
                }
                mma16(o[0], a0, a1, a2, a3, bv[0], bv[1]);
                mma16(o[1], a0, a1, a2, a3, bv[2], bv[3]);
            }
        }

        // ctx fp16 in [B,S,D] (D index = h*64 + d)
#pragma unroll
        for (int nb = 0; nb < 2; nb++) {
            int q = q0 + warpQ * 16 + g;
            int d = warpD * 16 + nb * 8 + 2 * tg;
            size_t base = ((size_t)b * SS + q) * DD + h * DK + d;
            *(__half2*)(g_ctxh + base)          = __floats2half2_rn(o[nb][0], o[nb][1]);
            *(__half2*)(g_ctxh + base + 8 * DD) = __floats2half2_rn(o[nb][2], o[nb][3]);
        }
    }
}

// ---------------------------------------------------------------------------
// Residual + LayerNorm (torch semantics: unbiased std, / (std + eps)).
// ---------------------------------------------------------------------------
__global__ void __launch_bounds__(256)
ln_kernel(const float* __restrict__ a, const float* __restrict__ r,
          const float* __restrict__ gamma, const float* __restrict__ beta,
          float* __restrict__ out, __half* __restrict__ oh)
{
    __shared__ float red[8];
    const int row = blockIdx.x;
    const int tid = threadIdx.x;
    const int warp = tid >> 5, lane = tid & 31;

    float4 va = ((const float4*)(a + (size_t)row * DD))[tid];
    float4 vr = ((const float4*)(r + (size_t)row * DD))[tid];
    float v0 = va.x + vr.x, v1 = va.y + vr.y, v2 = va.z + vr.z, v3 = va.w + vr.w;

    float s = v0 + v1 + v2 + v3;
#pragma unroll
    for (int o = 16; o; o >>= 1) s += __shfl_xor_sync(0xffffffffu, s, o);
    if (lane == 0) red[warp] = s;
    __syncthreads();
    float tot = 0.f;
#pragma unroll
    for (int i = 0; i < 8; i++) tot += red[i];
    float mean = tot * (1.0f / 1024.0f);
    __syncthreads();

    float d0 = v0 - mean, d1 = v1 - mean, d2 = v2 - mean, d3 = v3 - mean;
    float sq = d0 * d0 + d1 * d1 + d2 * d2 + d3 * d3;
#pragma unroll
    for (int o = 16; o; o >>= 1) sq += __shfl_xor_sync(0xffffffffu, sq, o);
    if (lane == 0) red[warp] = sq;
    __syncthreads();
    float tot2 = 0.f;
#pragma unroll
    for (int i = 0; i < 8; i++) tot2 += red[i];
    float var = tot2 * (1.0f / 1023.0f);         // ddof=1
    float inv = 1.0f / (sqrtf(var) + 1e-6f);      // (std + eps)

    float4 gm = ((const float4*)gamma)[tid];
    float4 bt = ((const float4*)beta)[tid];
    float4 o4;
    o4.x = gm.x * d0 * inv + bt.x;
    o4.y = gm.y * d1 * inv + bt.y;
    o4.z = gm.z * d2 * inv + bt.z;
    o4.w = gm.w * d3 * inv + bt.w;
    ((float4*)(out + (size_t)row * DD))[tid] = o4;
    if (oh) {
        size_t o = (size_t)row * DD + tid * 4;
        *(__half2*)(oh + o)     = __floats2half2_rn(o4.x, o4.y);
        *(__half2*)(oh + o + 2) = __floats2half2_rn(o4.z, o4.w);
    }
}

// ---------------------------------------------------------------------------
// Launch
// ---------------------------------------------------------------------------
extern "C" void kernel_launch(void* const* d_in, const int* in_sizes, int n_in,
                              void* d_out, int out_size)
{
    const float* x    = (const float*)d_in[0];
    const int*   mask = (const int*)  d_in[1];
    const float* adj  = (const float*)d_in[2];
    int base = (n_in > 3 && in_sizes[3] == 1) ? 4 : 3;
    const float* Wq = (const float*)d_in[base + 0];
    const float* bq = (const float*)d_in[base + 1];
    const float* Wk = (const float*)d_in[base + 2];
    const float* bk = (const float*)d_in[base + 3];
    const float* Wv = (const float*)d_in[base + 4];
    const float* bv = (const float*)d_in[base + 5];
    const float* Wo = (const float*)d_in[base + 6];
    const float* bo = (const float*)d_in[base + 7];
    const float* W1 = (const float*)d_in[base + 8];
    const float* b1 = (const float*)d_in[base + 9];
    const float* W2 = (const float*)d_in[base + 10];
    const float* b2 = (const float*)d_in[base + 11];
    const float* gm = (const float*)d_in[base + 12];
    const float* bt = (const float*)d_in[base + 13];
    float* out = (float*)d_out;

    float *tmp, *o1;
    __half *qh, *kh, *vh, *ctxh, *o1h, *hidh, *xh, *wt;
    cudaGetSymbolAddress((void**)&qh,   g_qh);
    cudaGetSymbolAddress((void**)&kh,   g_kh);
    cudaGetSymbolAddress((void**)&vh,   g_vh);
    cudaGetSymbolAddress((void**)&ctxh, g_ctxh);
    cudaGetSymbolAddress((void**)&tmp,  g_tmp);
    cudaGetSymbolAddress((void**)&o1,   g_o1);
    cudaGetSymbolAddress((void**)&o1h,  g_o1h);
    cudaGetSymbolAddress((void**)&hidh, g_hidh);
    cudaGetSymbolAddress((void**)&xh,   g_xh);
    cudaGetSymbolAddress((void**)&wt,   g_wt);

    cudaFuncSetAttribute(gemm_h<0>, cudaFuncAttributeMaxDynamicSharedMemorySize, GEMM_SMEM);
    cudaFuncSetAttribute(gemm_h<1>, cudaFuncAttributeMaxDynamicSharedMemorySize, GEMM_SMEM);
    cudaFuncSetAttribute(gemm_h<2>, cudaFuncAttributeMaxDynamicSharedMemorySize, GEMM_SMEM);
    cudaFuncSetAttribute(attn_kernel, cudaFuncAttributeMaxDynamicSharedMemorySize, ATTN_SMEM);

    // ---- preprocessing: fp16 conversions ----
    {
        int n4 = MM * DD / 4;
        hconv_kernel<<<(n4 + 255) / 256, 256>>>(x, xh, n4);
        wtrans4_kernel<<<dim3(DD/32, DD/32, 4), 256>>>(Wq, Wk, Wv, Wo, wt);
        wtrans_kernel<<<dim3(FF/32, DD/32), 256>>>(W1, wt + OFF_W1, DD, FF);
        wtrans_kernel<<<dim3(DD/32, FF/32), 256>>>(W2, wt + OFF_W2, FF, DD);
    }

    dim3 gQKV(3 * DD / 128, MM / 128);  // (24, 128)
    dim3 gD(DD / 128, MM / 128);        // (8, 128)
    dim3 gF(FF / 128, MM / 128);        // (32, 128)

    // fused QKV projection (rows 0..3071 of wt are Wq^T|Wk^T|Wv^T)
    gemm_h<2><<<gQKV, 256, GEMM_SMEM>>>(xh, wt, bq, bk, bv, 0, qh, kh, vh, MM, 3 * DD, DD);

    attn_kernel<<<dim3(SS / 32, HH, BB), 256, ATTN_SMEM>>>(adj, mask);

    gemm_h<0><<<gD, 256, GEMM_SMEM>>>(ctxh, wt + OFF_WO, bo, 0, 0, tmp, 0, 0, 0, MM, DD, DD);
    ln_kernel<<<MM, 256>>>(x, tmp, gm, bt, o1, o1h);

    gemm_h<1><<<gF, 256, GEMM_SMEM>>>(o1h, wt + OFF_W1, b1, 0, 0, 0, hidh, 0, 0, MM, FF, DD);
    gemm_h<0><<<gD, 256, GEMM_SMEM>>>(hidh, wt + OFF_W2, b2, 0, 0, tmp, 0, 0, 0, MM, DD, FF);
    ln_kernel<<<MM, 256>>>(o1, tmp, gm, bt, out, 0);
}

// round 17
// speedup vs baseline: 2.4735x; 1.1037x over previous
#include <cuda_runtime.h>
#include <cuda_fp16.h>
#include <cstdint>
#include <math.h>

// Problem dims (fixed by the reference)
#define BB 32
#define SS 512
#define DD 1024
#define HH 16
#define DK 64
#define FF 4096
#define MM (BB*SS)   // 16384 rows

// ---------------------------------------------------------------------------
// Scratch (static device arrays; no allocation APIs anywhere)
// ---------------------------------------------------------------------------
__device__ __half g_qh [BB*HH*SS*DK];   // [B,H,S,dk] fp16, Q pre-scaled by 1/8
__device__ __half g_kh [BB*HH*SS*DK];
__device__ __half g_vh [BB*HH*SS*DK];
__device__ __half g_ctxh[MM*DD];        // [B,S,D] fp16
__device__ float  g_tmp[MM*DD];         // attn_out / ffn_out (fp32)
__device__ float  g_o1 [MM*DD];         // out1 fp32 (residual)
__device__ __half g_o1h[MM*DD];         // out1 fp16 (GEMM input)
__device__ __half g_hidh[(size_t)MM*FF];// FFN hidden fp16
__device__ __half g_xh [MM*DD];         // x fp16
__device__ __half g_adjh[BB*SS*SS];     // adj fp16
__device__ __half g_wt [12582912];      // all 6 weights fp16, TRANSPOSED [N,K]

#define OFF_WQ 0
#define OFF_WK (OFF_WQ + DD*DD)
#define OFF_WV (OFF_WK + DD*DD)
#define OFF_WO (OFF_WV + DD*DD)
#define OFF_W1 (OFF_WO + DD*DD)
#define OFF_W2 (OFF_W1 + DD*FF)

// ---------------------------------------------------------------------------
// Helpers
// ---------------------------------------------------------------------------
__device__ __forceinline__ void mma16(float* c, uint32_t a0, uint32_t a1,
                                      uint32_t a2, uint32_t a3,
                                      uint32_t b0, uint32_t b1) {
    asm volatile(
        "mma.sync.aligned.m16n8k16.row.col.f32.f16.f16.f32 "
        "{%0,%1,%2,%3}, {%4,%5,%6,%7}, {%8,%9}, {%0,%1,%2,%3};\n"
        : "+f"(c[0]), "+f"(c[1]), "+f"(c[2]), "+f"(c[3])
        : "r"(a0), "r"(a1), "r"(a2), "r"(a3), "r"(b0), "r"(b1));
}

__device__ __forceinline__ void cpa16(uint32_t dst, const void* src) {
    asm volatile("cp.async.cg.shared.global [%0], [%1], 16;\n" :: "r"(dst), "l"(src));
}
#define CP_COMMIT() asm volatile("cp.async.commit_group;\n" ::: "memory")
#define CP_WAIT(n)  asm volatile("cp.async.wait_group %0;\n" :: "n"(n) : "memory")

__device__ __forceinline__ void ldmx4t(uint32_t& r0, uint32_t& r1,
                                       uint32_t& r2, uint32_t& r3, uint32_t addr) {
    asm volatile(
        "ldmatrix.sync.aligned.m8n8.x4.trans.shared.b16 {%0,%1,%2,%3}, [%4];"
        : "=r"(r0), "=r"(r1), "=r"(r2), "=r"(r3) : "r"(addr));
}

__device__ __forceinline__ float gelu_erf(float x) {
    return 0.5f * x * (1.0f + erff(x * 0.70710678118654752440f));
}

__device__ __forceinline__ uint32_t ldh32(const __half* p) {
    return *(const uint32_t*)p;
}

__device__ __forceinline__ uint32_t packh2(float a, float b) {
    __half2 h = __floats2half2_rn(a, b);
    return *reinterpret_cast<uint32_t*>(&h);
}

// ---------------------------------------------------------------------------
// Preprocessing: fp32 -> fp16 convert; transpose+convert weights to [N,K]
// ---------------------------------------------------------------------------
__global__ void __launch_bounds__(256)
hconv_kernel(const float* __restrict__ src, __half* __restrict__ dst, int n4)
{
    int i = blockIdx.x * 256 + threadIdx.x;
    if (i < n4) {
        float4 v = ((const float4*)src)[i];
        ((__half2*)dst)[i*2]   = __floats2half2_rn(v.x, v.y);
        ((__half2*)dst)[i*2+1] = __floats2half2_rn(v.z, v.w);
    }
}

__global__ void __launch_bounds__(256)
wtrans_kernel(const float* __restrict__ W, __half* __restrict__ Wt, int K, int N)
{
    __shared__ float t[32][33];
    int n0 = blockIdx.x * 32, k0 = blockIdx.y * 32;
    int tx = threadIdx.x & 31, ty = threadIdx.x >> 5;  // 32x8
#pragma unroll
    for (int j = 0; j < 4; j++)
        t[ty + j*8][tx] = W[(size_t)(k0 + ty + j*8) * N + n0 + tx];
    __syncthreads();
#pragma unroll
    for (int j = 0; j < 4; j++)
        Wt[(size_t)(n0 + ty + j*8) * K + k0 + tx] = __float2half(t[tx][ty + j*8]);
}

// Batched version for the four D x D weights (z selects the matrix)
__global__ void __launch_bounds__(256)
wtrans4_kernel(const float* __restrict__ W0, const float* __restrict__ W1,
               const float* __restrict__ W2, const float* __restrict__ W3,
               __half* __restrict__ Wt)
{
    __shared__ float t[32][33];
    const float* W = (blockIdx.z == 0) ? W0 : (blockIdx.z == 1) ? W1
                   : (blockIdx.z == 2) ? W2 : W3;
    __half* dst = Wt + (size_t)blockIdx.z * DD * DD;
    int n0 = blockIdx.x * 32, k0 = blockIdx.y * 32;
    int tx = threadIdx.x & 31, ty = threadIdx.x >> 5;
#pragma unroll
    for (int j = 0; j < 4; j++)
        t[ty + j*8][tx] = W[(size_t)(k0 + ty + j*8) * DD + n0 + tx];
    __syncthreads();
#pragma unroll
    for (int j = 0; j < 4; j++)
        dst[(size_t)(n0 + ty + j*8) * DD + k0 + tx] = __float2half(t[tx][ty + j*8]);
}

// ---------------------------------------------------------------------------
// FP16 GEMM: C[M,N] = A[M,K] @ Wt[N,K]^T + bias
//   EPI 0: fp32 store
//   EPI 1: GELU -> fp16 store (hidden)
//   EPI 2: fused QKV: per-CTA select {bias,dst,alpha} by n0>>10
// BM=128, BN=128, BK=32; 256 threads = 8 warps (2x4), warp tile 64x32.
// 4-stage cp.async; smem 80KB; __launch_bounds__(256,2) forces 2 CTAs/SM.
// ---------------------------------------------------------------------------
#define HST 40
#define STG_H (256*HST)
#define GEMM_SMEM (4*STG_H*2)

template <int EPI>
__global__ void __launch_bounds__(256, 2)
gemm_h(const __half* __restrict__ A, const __half* __restrict__ Bt,
       const float* __restrict__ bias0, const float* __restrict__ bias1,
       const float* __restrict__ bias2,
       float* __restrict__ Cf,
       __half* __restrict__ Ch0, __half* __restrict__ Ch1, __half* __restrict__ Ch2,
       int M, int N, int K)
{
    extern __shared__ __half hsm[];
    const uint32_t sb = (uint32_t)__cvta_generic_to_shared(hsm);

    const int tid  = threadIdx.x;
    const int m0   = blockIdx.y * 128;
    const int n0   = blockIdx.x * 128;
    const int warp = tid >> 5, lane = tid & 31;
    const int g    = lane >> 2, tg = lane & 3;
    const int warpM = warp & 1;
    const int warpN = warp >> 1;

    const int rlow = tid & 7, qc = (tid >> 3) & 3, w8 = tid >> 5;

    float acc[4][4][4];
#pragma unroll
    for (int a = 0; a < 4; a++)
#pragma unroll
        for (int b = 0; b < 4; b++)
#pragma unroll
            for (int c = 0; c < 4; c++) acc[a][b][c] = 0.f;

    const int nT = K / 32;

    auto issue = [&](int st, int c) {
        const int k0 = c * 32;
        const uint32_t base = sb + st * (STG_H * 2);
#pragma unroll
        for (int it = 0; it < 2; it++) {
            int r = rlow + 8 * w8 + 64 * it;
            cpa16(base + (uint32_t)(r * 80 + qc * 16),
                  A + (size_t)(m0 + r) * K + k0 + qc * 8);
            cpa16(base + (uint32_t)(128 * 80 + r * 80 + qc * 16),
                  Bt + (size_t)(n0 + r) * K + k0 + qc * 8);
        }
        CP_COMMIT();
    };

    issue(0, 0);
    issue(1, 1);
    issue(2, 2);

    for (int t = 0; t < nT; t++) {
        if (t + 3 < nT) CP_WAIT(2);
        else            CP_WAIT(0);
        __syncthreads();
        if (t + 3 < nT) issue((t + 3) & 3, t + 3);

        const __half* pA = hsm + (t & 3) * STG_H;
        const __half* pB = pA + 128 * HST;
#pragma unroll
        for (int ks = 0; ks < 2; ks++) {
            uint32_t af[4][4];
#pragma unroll
            for (int mf = 0; mf < 4; mf++) {
                int r = warpM * 64 + mf * 16 + g;
                int c = ks * 16 + 2 * tg;
                af[mf][0] = ldh32(pA + r * HST + c);
                af[mf][1] = ldh32(pA + (r + 8) * HST + c);
                af[mf][2] = ldh32(pA + r * HST + c + 8);
                af[mf][3] = ldh32(pA + (r + 8) * HST + c + 8);
            }
#pragma unroll
            for (int nf = 0; nf < 4; nf++) {
                int n = warpN * 32 + nf * 8 + g;
                int c = ks * 16 + 2 * tg;
                uint32_t b0 = ldh32(pB + n * HST + c);
                uint32_t b1 = ldh32(pB + n * HST + c + 8);
#pragma unroll
                for (int mf = 0; mf < 4; mf++)
                    mma16(acc[mf][nf], af[mf][0], af[mf][1], af[mf][2], af[mf][3], b0, b1);
            }
        }
    }

    // ---- epilogue ----
    const float* bias = bias0;
    __half* dstQKV = Ch0;
    float alpha = 1.0f;
    if (EPI == 2) {
        int which = n0 >> 10;
        bias   = (which == 0) ? bias0 : (which == 1 ? bias1 : bias2);
        dstQKV = (which == 0) ? Ch0   : (which == 1 ? Ch1   : Ch2);
        alpha  = (which == 0) ? 0.125f : 1.0f;
    }
#pragma unroll
    for (int mf = 0; mf < 4; mf++) {
#pragma unroll
        for (int nf = 0; nf < 4; nf++) {
            int row = m0 + warpM * 64 + mf * 16 + g;
            int col = n0 + warpN * 32 + nf * 8 + 2 * tg;
            int lcol = (EPI == 2) ? (col & 1023) : col;
            float b0 = bias[lcol], b1 = bias[lcol + 1];
            float v0 = acc[mf][nf][0] + b0;
            float v1 = acc[mf][nf][1] + b1;
            float v2 = acc[mf][nf][2] + b0;
            float v3 = acc[mf][nf][3] + b1;
            if (EPI == 0) {
                *(float2*)(Cf + (size_t)row * N + col)       = make_float2(v0, v1);
                *(float2*)(Cf + (size_t)(row + 8) * N + col) = make_float2(v2, v3);
            } else if (EPI == 1) {
                *(__half2*)(Ch0 + (size_t)row * N + col)       = __floats2half2_rn(gelu_erf(v0), gelu_erf(v1));
                *(__half2*)(Ch0 + (size_t)(row + 8) * N + col) = __floats2half2_rn(gelu_erf(v2), gelu_erf(v3));
            } else {
                int bI = row >> 9, s = row & 511;
                int h  = lcol >> 6, d = lcol & 63;
                size_t base = (((size_t)(bI * HH + h)) * SS + s) * DK + d;
                *(__half2*)(dstQKV + base)          = __floats2half2_rn(v0 * alpha, v1 * alpha);
                *(__half2*)(dstQKV + base + 8 * DK) = __floats2half2_rn(v2 * alpha, v3 * alpha);
            }
        }
    }
}

// ---------------------------------------------------------------------------
// Attention (FlashAttention-2 style): one CTA per (b, h, 64 q-rows), 128 thr,
// 4 warps x 16 rows. S kept in registers; online softmax (running max/sum,
// acc rescaling, deferred 1/l). K+adj and V double-buffered via cp.async.
// 63KB smem -> 3 CTAs/SM: softmax MUFU overlaps other warps' MMA.
// Commit order: K0,V0,K1,V1, then K(ch+2) after S, V(ch+2) after PV.
// ---------------------------------------------------------------------------
#define FA_KST 72                          // halves per row (144 B)
#define FA_KBUF 9216                       // 64 rows * 144 B
#define FA_K_OFF 9216                      // after Q (64*144)
#define FA_V_OFF (FA_K_OFF + 2*FA_KBUF)    // 27648
#define FA_ADJ_OFF (FA_V_OFF + 2*FA_KBUF)  // 46080
#define FA_SMEM (FA_ADJ_OFF + 2*FA_KBUF)   // 64512

__global__ void __launch_bounds__(128)
attn_kernel(const __half* __restrict__ adjh, const int* __restrict__ mask)
{
    extern __shared__ char smb[];
    __half* sQ = (__half*)smb;
    const uint32_t sbu = (uint32_t)__cvta_generic_to_shared(smb);
    __shared__ float sMaskB[SS];

    const int qt = blockIdx.x, h = blockIdx.y, b = blockIdx.z;
    const int q0 = qt * 64;
    const int tid = threadIdx.x;
    const int warp = tid >> 5, lane = tid & 31;
    const int g = lane >> 2, tg = lane & 3;
    const int r0 = warp * 16;

    const size_t headBase = ((size_t)(b * HH + h)) * SS * DK;
    const __half* adjBase = adjh + ((size_t)b * SS + q0) * SS;

    auto issueK = [&](int ch, int bf) {
#pragma unroll
        for (int i = 0; i < 4; i++) {
            int u = tid + i * 128;
            int r = u >> 3, c8 = u & 7;
            cpa16(sbu + FA_K_OFF + bf * FA_KBUF + (uint32_t)(r * 144 + c8 * 16),
                  g_kh + headBase + (size_t)(ch * 64 + r) * DK + c8 * 8);
            cpa16(sbu + FA_ADJ_OFF + bf * FA_KBUF + (uint32_t)(r * 144 + c8 * 16),
                  adjBase + (size_t)r * SS + ch * 64 + c8 * 8);
        }
        CP_COMMIT();
    };
    auto issueV = [&](int ch, int bf) {
#pragma unroll
        for (int i = 0; i < 4; i++) {
            int u = tid + i * 128;
            int r = u >> 3, c8 = u & 7;
            cpa16(sbu + FA_V_OFF + bf * FA_KBUF + (uint32_t)(r * 144 + c8 * 16),
                  g_vh + headBase + (size_t)(ch * 64 + r) * DK + c8 * 8);
        }
        CP_COMMIT();
    };

    issueK(0, 0); issueV(0, 0); issueK(1, 1); issueV(1, 1);

    // mask bias + Q tile (plain loads; visible after first barrier)
    for (int i = tid; i < SS; i += 128)
        sMaskB[i] = -1e9f * (float)mask[b * SS + i];
#pragma unroll
    for (int i = 0; i < 4; i++) {
        int s = tid + i * 128;
        int r = s >> 3, c8 = s & 7;
        *(uint4*)(sQ + r * FA_KST + c8 * 8) =
            *(const uint4*)(g_qh + headBase + (size_t)(q0 + r) * DK + c8 * 8);
    }

    float m0 = -1e30f, m1 = -1e30f, l0 = 0.f, l1 = 0.f;
    float acc[8][4];
#pragma unroll
    for (int i = 0; i < 8; i++)
#pragma unroll
        for (int j = 0; j < 4; j++) acc[i][j] = 0.f;

#pragma unroll 1
    for (int ch = 0; ch < 8; ch++) {
        // ---- wait K[ch] (+adj[ch]) ----
        if (ch < 7) CP_WAIT(3); else CP_WAIT(1);
        __syncthreads();
        const __half* sK   = (const __half*)(smb + FA_K_OFF + (ch & 1) * FA_KBUF);
        const __half* sAdj = (const __half*)(smb + FA_ADJ_OFF + (ch & 1) * FA_KBUF);

        // ---- S = Q K^T (registers) ----
        float s[8][4];
#pragma unroll
        for (int i = 0; i < 8; i++)
#pragma unroll
            for (int j = 0; j < 4; j++) s[i][j] = 0.f;
#pragma unroll
        for (int ks = 0; ks < 4; ks++) {
            int c = ks * 16 + 2 * tg;
            uint32_t a0 = ldh32(sQ + (r0 + g) * FA_KST + c);
            uint32_t a1 = ldh32(sQ + (r0 + g + 8) * FA_KST + c);
            uint32_t a2 = ldh32(sQ + (r0 + g) * FA_KST + c + 8);
            uint32_t a3 = ldh32(sQ + (r0 + g + 8) * FA_KST + c + 8);
#pragma unroll
            for (int nf = 0; nf < 8; nf++) {
                int n = nf * 8 + g;
                uint32_t b0 = ldh32(sK + n * FA_KST + c);
                uint32_t b1 = ldh32(sK + n * FA_KST + c + 8);
                mma16(s[nf], a0, a1, a2, a3, b0, b1);
            }
        }
        // ---- + mask bias + adj (reads sAdj: before buffer reuse) ----
#pragma unroll
        for (int nf = 0; nf < 8; nf++) {
            int colL = nf * 8 + 2 * tg;
            int colG = ch * 64 + colL;
            float mb0 = sMaskB[colG], mb1 = sMaskB[colG + 1];
            float2 f0 = __half22float2(*(const __half2*)(sAdj + (r0 + g) * FA_KST + colL));
            float2 f1 = __half22float2(*(const __half2*)(sAdj + (r0 + g + 8) * FA_KST + colL));
            s[nf][0] += mb0 + f0.x;
            s[nf][1] += mb1 + f0.y;
            s[nf][2] += mb0 + f1.x;
            s[nf][3] += mb1 + f1.y;
        }
        __syncthreads();                       // K/adj[ch] consumed by all warps
        if (ch + 2 < 8) issueK(ch + 2, ch & 1);

        // ---- online softmax (pure registers; overlaps other CTAs' MMA) ----
        float c0 = -1e30f, c1 = -1e30f;
#pragma unroll
        for (int nf = 0; nf < 8; nf++) {
            c0 = fmaxf(c0, fmaxf(s[nf][0], s[nf][1]));
            c1 = fmaxf(c1, fmaxf(s[nf][2], s[nf][3]));
        }
        c0 = fmaxf(c0, __shfl_xor_sync(0xffffffffu, c0, 1));
        c0 = fmaxf(c0, __shfl_xor_sync(0xffffffffu, c0, 2));
        c1 = fmaxf(c1, __shfl_xor_sync(0xffffffffu, c1, 1));
        c1 = fmaxf(c1, __shfl_xor_sync(0xffffffffu, c1, 2));
        float mn0 = fmaxf(m0, c0), mn1 = fmaxf(m1, c1);
        float sc0 = __expf(m0 - mn0), sc1 = __expf(m1 - mn1);
        m0 = mn0; m1 = mn1;
        float rs0 = 0.f, rs1 = 0.f;
#pragma unroll
        for (int nf = 0; nf < 8; nf++) {
            s[nf][0] = __expf(s[nf][0] - mn0);
            s[nf][1] = __expf(s[nf][1] - mn0);
            s[nf][2] = __expf(s[nf][2] - mn1);
            s[nf][3] = __expf(s[nf][3] - mn1);
            rs0 += s[nf][0] + s[nf][1];
            rs1 += s[nf][2] + s[nf][3];
        }
        rs0 += __shfl_xor_sync(0xffffffffu, rs0, 1);
        rs0 += __shfl_xor_sync(0xffffffffu, rs0, 2);
        rs1 += __shfl_xor_sync(0xffffffffu, rs1, 1);
        rs1 += __shfl_xor_sync(0xffffffffu, rs1, 2);
        l0 = l0 * sc0 + rs0;
        l1 = l1 * sc1 + rs1;
#pragma unroll
        for (int nf = 0; nf < 8; nf++) {
            acc[nf][0] *= sc0; acc[nf][1] *= sc0;
            acc[nf][2] *= sc1; acc[nf][3] *= sc1;
        }

        // ---- wait V[ch], PV ----
        if (ch < 6) CP_WAIT(3); else if (ch == 6) CP_WAIT(2); else CP_WAIT(0);
        __syncthreads();
        const uint32_t vbase = sbu + FA_V_OFF + (ch & 1) * FA_KBUF;
#pragma unroll
        for (int ks = 0; ks < 4; ks++) {
            uint32_t a0 = packh2(s[2*ks][0],   s[2*ks][1]);
            uint32_t a1 = packh2(s[2*ks][2],   s[2*ks][3]);
            uint32_t a2 = packh2(s[2*ks+1][0], s[2*ks+1][1]);
            uint32_t a3 = packh2(s[2*ks+1][2], s[2*ks+1][3]);
            int key = ks * 16 + (lane & 7) + (lane & 8);
#pragma unroll
            for (int db = 0; db < 4; db++) {
                int dmc = db * 16 + ((lane >> 4) << 3);
                uint32_t b0, b1, b2, b3;
                ldmx4t(b0, b1, b2, b3, vbase + (uint32_t)(key * 144 + dmc * 2));
                mma16(acc[db*2],     a0, a1, a2, a3, b0, b1);
                mma16(acc[db*2 + 1], a0, a1, a2, a3, b2, b3);
            }
        }
        __syncthreads();                       // V[ch] consumed by all warps
        if (ch + 2 < 8) issueV(ch + 2, ch & 1);
    }

    // ---- epilogue: ctx = acc / l, fp16 in [B,S,D] (D index = h*64 + d) ----
    float inv0 = 1.f / l0, inv1 = 1.f / l1;
#pragma unroll
    for (int db = 0; db < 4; db++) {
#pragma unroll
        for (int nb = 0; nb < 2; nb++) {
            int d = db * 16 + nb * 8 + 2 * tg;
            int q = q0 + r0 + g;
            size_t base = ((size_t)b * SS + q) * DD + h * DK + d;
            *(__half2*)(g_ctxh + base) =
                __floats2half2_rn(acc[db*2+nb][0] * inv0, acc[db*2+nb][1] * inv0);
            *(__half2*)(g_ctxh + base + 8 * DD) =
                __floats2half2_rn(acc[db*2+nb][2] * inv1, acc[db*2+nb][3] * inv1);
        }
    }
}

// ---------------------------------------------------------------------------
// Residual + LayerNorm (torch semantics: unbiased std, / (std + eps)).
// ---------------------------------------------------------------------------
__global__ void __launch_bounds__(256)
ln_kernel(const float* __restrict__ a, const float* __restrict__ r,
          const float* __restrict__ gamma, const float* __restrict__ beta,
          float* __restrict__ out, __half* __restrict__ oh)
{
    __shared__ float red[8];
    const int row = blockIdx.x;
    const int tid = threadIdx.x;
    const int warp = tid >> 5, lane = tid & 31;

    float4 va = ((const float4*)(a + (size_t)row * DD))[tid];
    float4 vr = ((const float4*)(r + (size_t)row * DD))[tid];
    float v0 = va.x + vr.x, v1 = va.y + vr.y, v2 = va.z + vr.z, v3 = va.w + vr.w;

    float s = v0 + v1 + v2 + v3;
#pragma unroll
    for (int o = 16; o; o >>= 1) s += __shfl_xor_sync(0xffffffffu, s, o);
    if (lane == 0) red[warp] = s;
    __syncthreads();
    float tot = 0.f;
#pragma unroll
    for (int i = 0; i < 8; i++) tot += red[i];
    float mean = tot * (1.0f / 1024.0f);
    __syncthreads();

    float d0 = v0 - mean, d1 = v1 - mean, d2 = v2 - mean, d3 = v3 - mean;
    float sq = d0 * d0 + d1 * d1 + d2 * d2 + d3 * d3;
#pragma unroll
    for (int o = 16; o; o >>= 1) sq += __shfl_xor_sync(0xffffffffu, sq, o);
    if (lane == 0) red[warp] = sq;
    __syncthreads();
    float tot2 = 0.f;
#pragma unroll
    for (int i = 0; i < 8; i++) tot2 += red[i];
    float var = tot2 * (1.0f / 1023.0f);         // ddof=1
    float inv = 1.0f / (sqrtf(var) + 1e-6f);      // (std + eps)

    float4 gm = ((const float4*)gamma)[tid];
    float4 bt = ((const float4*)beta)[tid];
    float4 o4;
    o4.x = gm.x * d0 * inv + bt.x;
    o4.y = gm.y * d1 * inv + bt.y;
    o4.z = gm.z * d2 * inv + bt.z;
    o4.w = gm.w * d3 * inv + bt.w;
    ((float4*)(out + (size_t)row * DD))[tid] = o4;
    if (oh) {
        size_t o = (size_t)row * DD + tid * 4;
        *(__half2*)(oh + o)     = __floats2half2_rn(o4.x, o4.y);
        *(__half2*)(oh + o + 2) = __floats2half2_rn(o4.z, o4.w);
    }
}

// ---------------------------------------------------------------------------
// Launch
// ---------------------------------------------------------------------------
extern "C" void kernel_launch(void* const* d_in, const int* in_sizes, int n_in,
                              void* d_out, int out_size)
{
    const float* x    = (const float*)d_in[0];
    const int*   mask = (const int*)  d_in[1];
    const float* adj  = (const float*)d_in[2];
    int base = (n_in > 3 && in_sizes[3] == 1) ? 4 : 3;
    const float* Wq = (const float*)d_in[base + 0];
    const float* bq = (const float*)d_in[base + 1];
    const float* Wk = (const float*)d_in[base + 2];
    const float* bk = (const float*)d_in[base + 3];
    const float* Wv = (const float*)d_in[base + 4];
    const float* bv = (const float*)d_in[base + 5];
    const float* Wo = (const float*)d_in[base + 6];
    const float* bo = (const float*)d_in[base + 7];
    const float* W1 = (const float*)d_in[base + 8];
    const float* b1 = (const float*)d_in[base + 9];
    const float* W2 = (const float*)d_in[base + 10];
    const float* b2 = (const float*)d_in[base + 11];
    const float* gm = (const float*)d_in[base + 12];
    const float* bt = (const float*)d_in[base + 13];
    float* out = (float*)d_out;

    float *tmp, *o1;
    __half *qh, *kh, *vh, *ctxh, *o1h, *hidh, *xh, *adjh, *wt;
    cudaGetSymbolAddress((void**)&qh,   g_qh);
    cudaGetSymbolAddress((void**)&kh,   g_kh);
    cudaGetSymbolAddress((void**)&vh,   g_vh);
    cudaGetSymbolAddress((void**)&ctxh, g_ctxh);
    cudaGetSymbolAddress((void**)&tmp,  g_tmp);
    cudaGetSymbolAddress((void**)&o1,   g_o1);
    cudaGetSymbolAddress((void**)&o1h,  g_o1h);
    cudaGetSymbolAddress((void**)&hidh, g_hidh);
    cudaGetSymbolAddress((void**)&xh,   g_xh);
    cudaGetSymbolAddress((void**)&adjh, g_adjh);
    cudaGetSymbolAddress((void**)&wt,   g_wt);

    cudaFuncSetAttribute(gemm_h<0>, cudaFuncAttributeMaxDynamicSharedMemorySize, GEMM_SMEM);
    cudaFuncSetAttribute(gemm_h<1>, cudaFuncAttributeMaxDynamicSharedMemorySize, GEMM_SMEM);
    cudaFuncSetAttribute(gemm_h<2>, cudaFuncAttributeMaxDynamicSharedMemorySize, GEMM_SMEM);
    cudaFuncSetAttribute(attn_kernel, cudaFuncAttributeMaxDynamicSharedMemorySize, FA_SMEM);

    // ---- preprocessing: fp16 conversions ----
    {
        int n4 = MM * DD / 4;
        hconv_kernel<<<(n4 + 255) / 256, 256>>>(x, xh, n4);
        int na = BB * SS * SS / 4;
        hconv_kernel<<<(na + 255) / 256, 256>>>(adj, adjh, na);
        wtrans4_kernel<<<dim3(DD/32, DD/32, 4), 256>>>(Wq, Wk, Wv, Wo, wt);
        wtrans_kernel<<<dim3(FF/32, DD/32), 256>>>(W1, wt + OFF_W1, DD, FF);
        wtrans_kernel<<<dim3(DD/32, FF/32), 256>>>(W2, wt + OFF_W2, FF, DD);
    }

    dim3 gQKV(3 * DD / 128, MM / 128);  // (24, 128)
    dim3 gD(DD / 128, MM / 128);        // (8, 128)
    dim3 gF(FF / 128, MM / 128);        // (32, 128)

    // fused QKV projection (rows 0..3071 of wt are Wq^T|Wk^T|Wv^T)
    gemm_h<2><<<gQKV, 256, GEMM_SMEM>>>(xh, wt, bq, bk, bv, 0, qh, kh, vh, MM, 3 * DD, DD);

    attn_kernel<<<dim3(SS / 64, HH, BB), 128, FA_SMEM>>>(adjh, mask);

    gemm_h<0><<<gD, 256, GEMM_SMEM>>>(ctxh, wt + OFF_WO, bo, 0, 0, tmp, 0, 0, 0, MM, DD, DD);
    ln_kernel<<<MM, 256>>>(x, tmp, gm, bt, o1, o1h);

    gemm_h<1><<<gF, 256, GEMM_SMEM>>>(o1h, wt + OFF_W1, b1, 0, 0, 0, hidh, 0, 0, MM, FF, DD);
    gemm_h<0><<<gD, 256, GEMM_SMEM>>>(hidh, wt + OFF_W2, b2, 0, 0, tmp, 0, 0, 0, MM, DD, FF);
    ln_kernel<<<MM, 256>>>(o1, tmp, gm, bt, out, 0);
}